// round 1
// baseline (speedup 1.0000x reference)
#include <cuda_runtime.h>
#include <math.h>

// Problem constants (fixed shapes for this benchmark)
#define B_   32
#define SSRC 512
#define D_   512
#define STR_ 4
#define T_   2048      // SSRC*STR_
#define V_   512
#define L_   256
#define S_   513       // 2*L+1
#define SP_  520       // padded S stride (multiple of 4 for float4)
#define CH_  8
#define NC_  (T_/CH_)

// -------------------- scratch (device globals; no allocations allowed) ----
__device__ float g_states[(size_t)16384 * 2048];   // GEMM1 out == states; reused for logits (65536*512)
__device__ float g_H[(size_t)65536 * 1024];        // hidden
__device__ float g_Pext[(size_t)B_ * T_ * SP_];    // gathered, max-normalized probs
__device__ float g_mt[B_ * T_];                    // per-(b,t) max log-prob over ext labels
__device__ float g_Msum[B_];
__device__ int   g_tlen[B_];
__device__ int   g_olen[B_];

// -------------------- small reduce helpers --------------------------------
__device__ __forceinline__ float warpReduceMaxF(float v) {
#pragma unroll
    for (int o = 16; o > 0; o >>= 1) v = fmaxf(v, __shfl_xor_sync(0xffffffffu, v, o));
    return v;
}
__device__ __forceinline__ float warpReduceSumF(float v) {
#pragma unroll
    for (int o = 16; o > 0; o >>= 1) v += __shfl_xor_sync(0xffffffffu, v, o);
    return v;
}
__device__ __forceinline__ int warpReduceSumI(int v) {
#pragma unroll
    for (int o = 16; o > 0; o >>= 1) v += __shfl_xor_sync(0xffffffffu, v, o);
    return v;
}

// -------------------- SGEMM: C[M,N] = A[M,K] @ B[K,N] + bias (opt relu) ---
// 128x128 tile, BK=8, 256 threads, 8x8 per-thread microtile.
template <bool RELU>
__global__ __launch_bounds__(256) void sgemm128(
    const float* __restrict__ A, const float* __restrict__ Bm,
    const float* __restrict__ bias, float* __restrict__ C,
    int M, int N, int K)
{
    __shared__ float As[8][128];
    __shared__ float Bs[8][128];
    const int tid  = threadIdx.x;
    const int brow = blockIdx.y, bcol = blockIdx.x;
    const float* Ablk = A + (size_t)brow * 128 * K;
    const float* Bblk = Bm + (size_t)bcol * 128;

    const int aRow = tid >> 1;          // 0..127
    const int aCol = (tid & 1) * 4;     // 0 or 4
    const int bRow = tid >> 5;          // 0..7
    const int bCol = (tid & 31) * 4;    // 0..124
    const int ty = tid >> 4;            // 0..15
    const int tx = tid & 15;            // 0..15

    float acc[8][8];
#pragma unroll
    for (int i = 0; i < 8; i++)
#pragma unroll
        for (int j = 0; j < 8; j++) acc[i][j] = 0.f;

    for (int k0 = 0; k0 < K; k0 += 8) {
        float4 av = *(const float4*)(Ablk + (size_t)aRow * K + k0 + aCol);
        float4 bv = *(const float4*)(Bblk + (size_t)(k0 + bRow) * N + bCol);
        __syncthreads();
        As[aCol + 0][aRow] = av.x;
        As[aCol + 1][aRow] = av.y;
        As[aCol + 2][aRow] = av.z;
        As[aCol + 3][aRow] = av.w;
        *(float4*)&Bs[bRow][bCol] = bv;
        __syncthreads();
#pragma unroll
        for (int kk = 0; kk < 8; kk++) {
            float4 a0 = *(const float4*)&As[kk][ty * 8];
            float4 a1 = *(const float4*)&As[kk][ty * 8 + 4];
            float4 b0 = *(const float4*)&Bs[kk][tx * 8];
            float4 b1 = *(const float4*)&Bs[kk][tx * 8 + 4];
            float a[8] = {a0.x, a0.y, a0.z, a0.w, a1.x, a1.y, a1.z, a1.w};
            float bb[8] = {b0.x, b0.y, b0.z, b0.w, b1.x, b1.y, b1.z, b1.w};
#pragma unroll
            for (int i = 0; i < 8; i++)
#pragma unroll
                for (int j = 0; j < 8; j++) acc[i][j] += a[i] * bb[j];
        }
    }

    const int row0 = brow * 128 + ty * 8;
    const int col0 = bcol * 128 + tx * 8;
    float bvals[8];
#pragma unroll
    for (int j = 0; j < 8; j++) bvals[j] = bias[col0 + j];
#pragma unroll
    for (int i = 0; i < 8; i++) {
#pragma unroll
        for (int j = 0; j < 8; j++) {
            float v = acc[i][j] + bvals[j];
            if (RELU) v = fmaxf(v, 0.f);
            C[(size_t)(row0 + i) * N + col0 + j] = v;
        }
    }
}

// -------------------- fused log-softmax + label gather --------------------
// One block per (b,t) row. Writes logprobs to d_out, Phat to g_Pext, m_t to g_mt.
__global__ __launch_bounds__(256) void softmax_gather_kernel(
    const float* __restrict__ logits, const int* __restrict__ targets,
    float* __restrict__ lp_out, float* __restrict__ Pext, float* __restrict__ mt)
{
    const int row = blockIdx.x;       // b*T + t
    const int b   = row >> 11;        // T_ = 2048
    const int tid = threadIdx.x;
    const int lane = tid & 31, wid = tid >> 5;
    const float* x = logits + (size_t)row * V_;

    __shared__ float sh_e[V_];
    __shared__ float sh_g[S_];
    __shared__ float red[8];

    float v0 = x[tid];
    float v1 = x[tid + 256];
    float m = fmaxf(v0, v1);
    m = warpReduceMaxF(m);
    if (lane == 0) red[wid] = m;
    __syncthreads();
    float mm = red[0];
#pragma unroll
    for (int i = 1; i < 8; i++) mm = fmaxf(mm, red[i]);
    __syncthreads();   // before red reuse

    float e0 = __expf(v0 - mm), e1 = __expf(v1 - mm);
    sh_e[tid] = e0;
    sh_e[tid + 256] = e1;
    float sm = warpReduceSumF(e0 + e1);
    if (lane == 0) red[wid] = sm;
    __syncthreads();   // also makes sh_e visible
    float ssum = red[0];
#pragma unroll
    for (int i = 1; i < 8; i++) ssum += red[i];

    float lse = __logf(ssum);
    lp_out[(size_t)row * V_ + tid] = v0 - mm - lse;
    lp_out[(size_t)row * V_ + tid + 256] = v1 - mm - lse;

    // gather probs for extended labels
    float pm = 0.f;
    for (int s = tid; s < S_; s += 256) {
        int lab = (s & 1) ? targets[b * L_ + (s >> 1)] : 1;  // BLANK=1
        float p = sh_e[lab];
        sh_g[s] = p;
        pm = fmaxf(pm, p);
    }
    pm = warpReduceMaxF(pm);
    __syncthreads();   // before red reuse
    if (lane == 0) red[wid] = pm;
    __syncthreads();
    float pmax = red[0];
#pragma unroll
    for (int i = 1; i < 8; i++) pmax = fmaxf(pmax, red[i]);
    float inv = 1.0f / pmax;
    for (int s = tid; s < S_; s += 256)
        Pext[(size_t)row * SP_ + s] = sh_g[s] * inv;
    if (tid == 0) mt[row] = __logf(pmax) - lse;
}

// -------------------- lengths + output init --------------------------------
__global__ __launch_bounds__(256) void lengths_kernel(
    const int* __restrict__ encm, const int* __restrict__ tgtm,
    float* __restrict__ out, int len_off, int loss_off,
    int* __restrict__ tlen, int* __restrict__ olen)
{
    const int b = blockIdx.x, tid = threadIdx.x;
    const int lane = tid & 31, wid = tid >> 5;
    int c1 = 0;
    for (int i = tid; i < SSRC; i += 256) c1 += (encm[b * SSRC + i] != 0);
    int c2 = 0;
    for (int i = tid; i < L_; i += 256) c2 += (tgtm[b * L_ + i] != 0);
    c1 = warpReduceSumI(c1);
    c2 = warpReduceSumI(c2);
    __shared__ int redi[16];
    if (lane == 0) { redi[wid] = c1; redi[8 + wid] = c2; }
    __syncthreads();
    if (tid == 0) {
        int a = 0, t = 0;
#pragma unroll
        for (int i = 0; i < 8; i++) { a += redi[i]; t += redi[8 + i]; }
        olen[b] = STR_ * a;
        tlen[b] = t;
        out[len_off + b] = (float)(STR_ * a);
        if (b == 0) out[loss_off] = 0.f;
    }
}

// -------------------- sum of m_t over valid timesteps ----------------------
__global__ __launch_bounds__(256) void msum_kernel(
    const float* __restrict__ mt, const int* __restrict__ olen,
    float* __restrict__ Msum)
{
    const int b = blockIdx.x, tid = threadIdx.x;
    int il = olen[b]; if (il > T_) il = T_;
    float sacc = 0.f;
    for (int t = tid; t < il; t += 256) sacc += mt[b * T_ + t];
    sacc = warpReduceSumF(sacc);
    __shared__ float red[8];
    if ((tid & 31) == 0) red[tid >> 5] = sacc;
    __syncthreads();
    if (tid == 0) {
        float r = 0.f;
#pragma unroll
        for (int i = 0; i < 8; i++) r += red[i];
        Msum[b] = r;
    }
}

// -------------------- CTC forward DP (probability domain) ------------------
// One block per batch element, 544 threads (17 warps), 1 state per thread.
// alpha_hat updated as (a + a1 + skip*a2) * Phat, renormalized by block-max
// every CH_ steps; log scale corrections accumulated in thread 0.
__global__ __launch_bounds__(544) void ctc_dp_kernel(
    const float* __restrict__ Pext, const float* __restrict__ Msum,
    const int* __restrict__ targets, const int* __restrict__ tlen,
    const int* __restrict__ olen, float* __restrict__ loss_slot)
{
    const int b = blockIdx.x;
    const int tid = threadIdx.x;
    __shared__ float sa[546];                       // sa[0..1] = pad zeros; state s at sa[2+s]
    __shared__ __align__(16) float buf[2][CH_][SP_]; // double-buffered Phat chunks
    __shared__ float warpred[17];
    __shared__ float s_inv;

    const int s = tid;
    const bool active = (s < S_);
    bool skip = false;
    if (active && (s & 1)) {
        int l = s >> 1;
        int tc = targets[b * L_ + l];
        bool ok = (tc != 1);
        if (l > 0) ok = ok && (tc != targets[b * L_ + l - 1]);
        skip = ok;
    }
    const int inlen = olen[b];
    const int tl = tlen[b];

    sa[tid] = 0.f;
    if (tid < 2) sa[544 + tid] = 0.f;

    const float* Pb = Pext + (size_t)b * T_ * SP_;
    const int li0 = tid, li1 = tid + 544;           // float4 indices into 1040-float4 chunk
    float4 r0 = make_float4(0.f, 0.f, 0.f, 0.f), r1 = r0;
    {
        const float4* src = (const float4*)Pb;
        if (li0 < 1040) r0 = src[li0];
        if (li1 < 1040) r1 = src[li1];
        float4* dst = (float4*)&buf[0][0][0];
        if (li0 < 1040) dst[li0] = r0;
        if (li1 < 1040) dst[li1] = r1;
    }
    __syncthreads();

    float Cacc = 0.f;  // meaningful on thread 0 only
    for (int c = 0; c < NC_; c++) {
        if (c + 1 < NC_) {  // prefetch next chunk (latency hidden under compute)
            const float4* src = (const float4*)(Pb + (size_t)(c + 1) * CH_ * SP_);
            if (li0 < 1040) r0 = src[li0];
            if (li1 < 1040) r1 = src[li1];
        }
        const int cur = c & 1;
#pragma unroll
        for (int tr = 0; tr < CH_; tr++) {
            const int tg = c * CH_ + tr;
            float val = 0.f;
            if (active) {
                float P = buf[cur][tr][s];
                if (tg == 0) {
                    val = (s == 0 || (s == 1 && tl > 0)) ? P : 0.f;
                } else {
                    float a  = sa[2 + s];
                    float a1 = sa[1 + s];
                    float a2 = skip ? sa[s] : 0.f;
                    val = (a + a1 + a2) * P;
                }
            }
            __syncthreads();
            if (active && (tg == 0 || tg < inlen)) sa[2 + s] = val;
            __syncthreads();
        }
        if (c + 1 < NC_) {
            float4* dst = (float4*)&buf[cur ^ 1][0][0];
            if (li0 < 1040) dst[li0] = r0;
            if (li1 < 1040) dst[li1] = r1;
        }
        // renorm every chunk (8 steps); its barriers also protect the buf write
        float mv = active ? sa[2 + s] : 0.f;
        mv = warpReduceMaxF(mv);
        if ((tid & 31) == 0) warpred[tid >> 5] = mv;
        __syncthreads();
        if (tid == 0) {
            float r = warpred[0];
#pragma unroll
            for (int i = 1; i < 17; i++) r = fmaxf(r, warpred[i]);
            if (r > 0.f) { s_inv = 1.0f / r; Cacc += __logf(r); }
            else s_inv = 1.0f;
        }
        __syncthreads();
        if (active) sa[2 + s] *= s_inv;
        __syncthreads();
    }

    if (tid == 0) {
        int il2 = 2 * tl;
        float al = sa[2 + il2];
        float ap = (tl > 0) ? sa[2 + il2 - 1] : 0.f;
        float per = -(__logf(al + ap) + Cacc + Msum[b]);
        float tld = (float)(tl > 0 ? tl : 1);
        atomicAdd(loss_slot, per / (tld * (float)B_));
    }
}

__global__ void finalize_kernel(float* out, int loss_off)
{
    float v = out[loss_off];
    if (!isfinite(v)) out[loss_off] = 0.f;
}

// -------------------- launch ------------------------------------------------
extern "C" void kernel_launch(void* const* d_in, const int* in_sizes, int n_in,
                              void* d_out, int out_size)
{
    const float* rep  = (const float*)d_in[0];
    const int*   encm = (const int*)d_in[1];
    const int*   tgt  = (const int*)d_in[2];
    const int*   tgtm = (const int*)d_in[3];
    const float* Wexp = (const float*)d_in[4];
    const float* bexp = (const float*)d_in[5];
    const float* W1   = (const float*)d_in[6];
    const float* b1   = (const float*)d_in[7];
    const float* W2   = (const float*)d_in[8];
    const float* b2   = (const float*)d_in[9];
    float* out = (float*)d_out;

    float *p_states, *p_H, *p_Pext, *p_mt, *p_Msum;
    int *p_tlen, *p_olen;
    cudaGetSymbolAddress((void**)&p_states, g_states);
    cudaGetSymbolAddress((void**)&p_H, g_H);
    cudaGetSymbolAddress((void**)&p_Pext, g_Pext);
    cudaGetSymbolAddress((void**)&p_mt, g_mt);
    cudaGetSymbolAddress((void**)&p_Msum, g_Msum);
    cudaGetSymbolAddress((void**)&p_tlen, g_tlen);
    cudaGetSymbolAddress((void**)&p_olen, g_olen);

    const int M1 = B_ * SSRC,  N1 = STR_ * D_, K1 = D_;    // 16384 x 2048 x 512
    const int M2 = B_ * T_,    N2 = 2 * D_,    K2 = D_;    // 65536 x 1024 x 512
    const int M3 = B_ * T_,    N3 = V_,        K3 = 2*D_;  // 65536 x 512 x 1024

    dim3 blk(256);
    // states = rep @ W_exp + b_exp  (flat memory == reshaped [B, T, D])
    sgemm128<false><<<dim3(N1 / 128, M1 / 128), blk>>>(rep, Wexp, bexp, p_states, M1, N1, K1);
    // H = relu(states @ W1 + b1)
    sgemm128<true ><<<dim3(N2 / 128, M2 / 128), blk>>>(p_states, W1, b1, p_H, M2, N2, K2);
    // logits = H @ W2 + b2   (reuse g_states as logits buffer)
    sgemm128<false><<<dim3(N3 / 128, M3 / 128), blk>>>(p_H, W2, b2, p_states, M3, N3, K3);

    const int loss_off = out_size - 1;
    const int len_off  = out_size - 1 - B_;
    lengths_kernel<<<B_, 256>>>(encm, tgtm, out, len_off, loss_off, p_tlen, p_olen);
    softmax_gather_kernel<<<B_ * T_, 256>>>(p_states, tgt, out, p_Pext, p_mt);
    msum_kernel<<<B_, 256>>>(p_mt, p_olen, p_Msum);
    ctc_dp_kernel<<<B_, 544>>>(p_Pext, p_Msum, tgt, p_tlen, p_olen, out + loss_off);
    finalize_kernel<<<1, 1>>>(out, loss_off);
}

// round 4
// speedup vs baseline: 2.1488x; 2.1488x over previous
#include <cuda_runtime.h>
#include <cuda_bf16.h>
#include <math.h>
#include <stdint.h>

// Problem constants
#define B_   32
#define SSRC 512
#define D_   512
#define STR_ 4
#define T_   2048
#define V_   512
#define L_   256
#define S_   513
#define SP_  520
#define CH_  8
#define NC_  (T_/CH_)

// -------------------- scratch (device globals) ----------------------------
__device__ __nv_bfloat16 g_reph[(size_t)16384 * 512];
__device__ __nv_bfloat16 g_repl[(size_t)16384 * 512];
__device__ __nv_bfloat16 g_Wexpt_h[(size_t)2048 * 512];
__device__ __nv_bfloat16 g_Wexpt_l[(size_t)2048 * 512];
__device__ __nv_bfloat16 g_W1t_h[(size_t)1024 * 512];
__device__ __nv_bfloat16 g_W1t_l[(size_t)1024 * 512];
__device__ __nv_bfloat16 g_W2t_h[(size_t)512 * 1024];
__device__ __nv_bfloat16 g_W2t_l[(size_t)512 * 1024];
__device__ __nv_bfloat16 g_sth[(size_t)16384 * 2048];  // states hi
__device__ __nv_bfloat16 g_stl[(size_t)16384 * 2048];
__device__ __nv_bfloat16 g_Hh[(size_t)65536 * 1024];
__device__ __nv_bfloat16 g_Hl[(size_t)65536 * 1024];
__device__ float g_logits[(size_t)65536 * 512];
__device__ float g_Pext[(size_t)B_ * T_ * SP_];
__device__ float g_mt[B_ * T_];
__device__ float g_Msum[B_];
__device__ int   g_tlen[B_];
__device__ int   g_olen[B_];

// -------------------- helpers ---------------------------------------------
__device__ __forceinline__ float warpReduceMaxF(float v) {
#pragma unroll
    for (int o = 16; o > 0; o >>= 1) v = fmaxf(v, __shfl_xor_sync(0xffffffffu, v, o));
    return v;
}
__device__ __forceinline__ float warpReduceSumF(float v) {
#pragma unroll
    for (int o = 16; o > 0; o >>= 1) v += __shfl_xor_sync(0xffffffffu, v, o);
    return v;
}
__device__ __forceinline__ int warpReduceSumI(int v) {
#pragma unroll
    for (int o = 16; o > 0; o >>= 1) v += __shfl_xor_sync(0xffffffffu, v, o);
    return v;
}
__device__ __forceinline__ unsigned short f2bf(float v) {
    __nv_bfloat16 h = __float2bfloat16(v);
    return *reinterpret_cast<unsigned short*>(&h);
}
__device__ __forceinline__ float bf2f(unsigned short u) {
    __nv_bfloat16 h = *reinterpret_cast<__nv_bfloat16*>(&u);
    return __bfloat162float(h);
}
__device__ __forceinline__ uint32_t smem_u32(const void* p) {
    uint32_t a;
    asm("{ .reg .u64 t; cvta.to.shared.u64 t, %1; cvt.u32.u64 %0, t; }" : "=r"(a) : "l"(p));
    return a;
}
__device__ __forceinline__ uint32_t swz128(uint32_t x) { return x ^ ((x >> 3) & 0x70u); }

__device__ __forceinline__ void cpa16(uint32_t dst, const void* src) {
    asm volatile("cp.async.cg.shared.global [%0], [%1], 16;" :: "r"(dst), "l"(src));
}
#define CP_COMMIT() asm volatile("cp.async.commit_group;" ::: "memory")
#define CP_WAIT0()  asm volatile("cp.async.wait_group 0;" ::: "memory")

__device__ __forceinline__ void ldsm4(uint32_t* r, uint32_t a) {
    asm volatile("ldmatrix.sync.aligned.m8n8.x4.shared.b16 {%0,%1,%2,%3}, [%4];"
        : "=r"(r[0]), "=r"(r[1]), "=r"(r[2]), "=r"(r[3]) : "r"(a));
}
__device__ __forceinline__ void mma16816(float* c, const uint32_t* a, uint32_t b0, uint32_t b1) {
    asm volatile("mma.sync.aligned.m16n8k16.row.col.f32.bf16.bf16.f32 "
        "{%0,%1,%2,%3}, {%4,%5,%6,%7}, {%8,%9}, {%0,%1,%2,%3};"
        : "+f"(c[0]), "+f"(c[1]), "+f"(c[2]), "+f"(c[3])
        : "r"(a[0]), "r"(a[1]), "r"(a[2]), "r"(a[3]), "r"(b0), "r"(b1));
}

// -------------------- input conversion kernels -----------------------------
__global__ __launch_bounds__(256) void conv_rep_kernel(
    const float* __restrict__ x, __nv_bfloat16* __restrict__ h,
    __nv_bfloat16* __restrict__ l)
{
    int i = blockIdx.x * 256 + threadIdx.x;
    float4 v = ((const float4*)x)[i];
    ushort4 hs, ls;
    hs.x = f2bf(v.x); ls.x = f2bf(v.x - bf2f(hs.x));
    hs.y = f2bf(v.y); ls.y = f2bf(v.y - bf2f(hs.y));
    hs.z = f2bf(v.z); ls.z = f2bf(v.z - bf2f(hs.z));
    hs.w = f2bf(v.w); ls.w = f2bf(v.w - bf2f(hs.w));
    ((ushort4*)h)[i] = hs;
    ((ushort4*)l)[i] = ls;
}

// W [K,N] row-major -> T [N,K] bf16 hi/lo
__global__ __launch_bounds__(256) void wtrans_kernel(
    const float* __restrict__ W, __nv_bfloat16* __restrict__ Th,
    __nv_bfloat16* __restrict__ Tl, int K, int N)
{
    __shared__ float tile[32][33];
    const int bx = blockIdx.x, by = blockIdx.y;
    const int tx = threadIdx.x & 31, ty = threadIdx.x >> 5;
#pragma unroll
    for (int i = 0; i < 4; i++)
        tile[ty + i * 8][tx] = W[(size_t)(by * 32 + ty + i * 8) * N + bx * 32 + tx];
    __syncthreads();
#pragma unroll
    for (int i = 0; i < 4; i++) {
        float v = tile[tx][ty + i * 8];
        unsigned short h = f2bf(v);
        unsigned short lo = f2bf(v - bf2f(h));
        size_t o = (size_t)(bx * 32 + ty + i * 8) * K + by * 32 + tx;
        ((unsigned short*)Th)[o] = h;
        ((unsigned short*)Tl)[o] = lo;
    }
}

// -------------------- mma.sync split-bf16 GEMM -----------------------------
// C[M,N] = (Ah+Al)[M,K] @ (Bh+Bl)[N,K]^T + bias (3-product split, fp32 acc).
// Block 128x128, K-chunk 64, 256 threads, warp tile 32x64.
template <bool RELU, bool OUTF32>
__global__ __launch_bounds__(256) void gemm_mma(
    const __nv_bfloat16* __restrict__ Ah, const __nv_bfloat16* __restrict__ Al,
    const __nv_bfloat16* __restrict__ Bh, const __nv_bfloat16* __restrict__ Bl,
    const float* __restrict__ bias,
    __nv_bfloat16* __restrict__ Ch, __nv_bfloat16* __restrict__ Cl,
    float* __restrict__ Cf, int M, int N, int K)
{
    extern __shared__ __align__(16) char dsm[];   // 2 stages x 65536
    const uint32_t sbase = smem_u32(dsm);
    const int tid = threadIdx.x;
    const int lane = tid & 31, w = tid >> 5;
    const int m0 = blockIdx.y * 128;
    const int n0 = blockIdx.x * 128;
    const int wm0 = (w >> 1) * 32;
    const int wn0 = (w & 1) * 64;
    const int nch = K >> 6;

    const int lrow = tid >> 3;        // 0..31
    const int lcg  = tid & 7;         // 16B group within 128B row
    const char* pAh = (const char*)Ah;
    const char* pAl = (const char*)Al;
    const char* pBh = (const char*)Bh;
    const char* pBl = (const char*)Bl;

#define ISSUE(k0, st)                                                          \
    {                                                                          \
        uint32_t sb = sbase + (st) * 65536;                                    \
        _Pragma("unroll")                                                      \
        for (int j = 0; j < 4; j++) {                                          \
            int r = lrow + j * 32;                                             \
            uint32_t so = swz128((uint32_t)(r * 128 + lcg * 16));              \
            size_t goA = ((size_t)(m0 + r) * K + (k0) + lcg * 8) * 2;          \
            size_t goB = ((size_t)(n0 + r) * K + (k0) + lcg * 8) * 2;          \
            cpa16(sb + so, pAh + goA);                                         \
            cpa16(sb + 16384 + so, pAl + goA);                                 \
            cpa16(sb + 32768 + so, pBh + goB);                                 \
            cpa16(sb + 49152 + so, pBl + goB);                                 \
        }                                                                      \
    }

    float acc[2][8][4];
#pragma unroll
    for (int mt = 0; mt < 2; mt++)
#pragma unroll
        for (int nt = 0; nt < 8; nt++)
#pragma unroll
            for (int q = 0; q < 4; q++) acc[mt][nt][q] = 0.f;

    ISSUE(0, 0);
    CP_COMMIT();
    CP_WAIT0();
    __syncthreads();

    const int rl = ((lane >> 3) & 1) * 8 + (lane & 7);
    const int kb = (lane >> 4) * 8;

#pragma unroll 1
    for (int c = 0; c < nch; c++) {
        const int st = c & 1;
        if (c + 1 < nch) { ISSUE((c + 1) << 6, st ^ 1); CP_COMMIT(); }

        const uint32_t ah_b = sbase + st * 65536;
        const uint32_t al_b = ah_b + 16384;
        const uint32_t bh_b = ah_b + 32768;
        const uint32_t bl_b = ah_b + 49152;
#pragma unroll
        for (int ks = 0; ks < 4; ks++) {
            const uint32_t kof = (uint32_t)((ks * 16 + kb) * 2);
            uint32_t aH[2][4], aL[2][4];
#pragma unroll
            for (int mt = 0; mt < 2; mt++) {
                uint32_t off = swz128((uint32_t)((wm0 + mt * 16 + rl) * 128) + kof);
                ldsm4(aH[mt], ah_b + off);
                ldsm4(aL[mt], al_b + off);
            }
            uint32_t bH[4][4], bL[4][4];
#pragma unroll
            for (int ng = 0; ng < 4; ng++) {
                uint32_t off = swz128((uint32_t)((wn0 + ng * 16 + rl) * 128) + kof);
                ldsm4(bH[ng], bh_b + off);
                ldsm4(bL[ng], bl_b + off);
            }
#pragma unroll
            for (int mt = 0; mt < 2; mt++)
#pragma unroll
                for (int nt = 0; nt < 8; nt++) {
                    const int ng = nt >> 1, sl = nt & 1;
                    mma16816(acc[mt][nt], aH[mt], bH[ng][sl], bH[ng][sl + 2]);
                    mma16816(acc[mt][nt], aH[mt], bL[ng][sl], bL[ng][sl + 2]);
                    mma16816(acc[mt][nt], aL[mt], bH[ng][sl], bH[ng][sl + 2]);
                }
        }
        if (c + 1 < nch) { CP_WAIT0(); __syncthreads(); }
    }

    // epilogue
#pragma unroll
    for (int mt = 0; mt < 2; mt++) {
#pragma unroll
        for (int nt = 0; nt < 8; nt++) {
            const int row = m0 + wm0 + mt * 16 + (lane >> 2);
            const int col = n0 + wn0 + nt * 8 + (lane & 3) * 2;
            float bv0 = __ldg(bias + col);
            float bv1 = __ldg(bias + col + 1);
            float v00 = acc[mt][nt][0] + bv0;
            float v01 = acc[mt][nt][1] + bv1;
            float v10 = acc[mt][nt][2] + bv0;
            float v11 = acc[mt][nt][3] + bv1;
            if (RELU) {
                v00 = fmaxf(v00, 0.f); v01 = fmaxf(v01, 0.f);
                v10 = fmaxf(v10, 0.f); v11 = fmaxf(v11, 0.f);
            }
            size_t g0 = (size_t)row * N + col;
            size_t g1 = (size_t)(row + 8) * N + col;
            if (OUTF32) {
                *(float2*)(Cf + g0) = make_float2(v00, v01);
                *(float2*)(Cf + g1) = make_float2(v10, v11);
            } else {
                ushort2 h0, l0, h1, l1;
                h0.x = f2bf(v00); l0.x = f2bf(v00 - bf2f(h0.x));
                h0.y = f2bf(v01); l0.y = f2bf(v01 - bf2f(h0.y));
                h1.x = f2bf(v10); l1.x = f2bf(v10 - bf2f(h1.x));
                h1.y = f2bf(v11); l1.y = f2bf(v11 - bf2f(h1.y));
                *(ushort2*)((unsigned short*)Ch + g0) = h0;
                *(ushort2*)((unsigned short*)Cl + g0) = l0;
                *(ushort2*)((unsigned short*)Ch + g1) = h1;
                *(ushort2*)((unsigned short*)Cl + g1) = l1;
            }
        }
    }
#undef ISSUE
}

// -------------------- fused log-softmax + label gather ---------------------
__global__ __launch_bounds__(256) void softmax_gather_kernel(
    const float* __restrict__ logits, const int* __restrict__ targets,
    float* __restrict__ lp_out, float* __restrict__ Pext, float* __restrict__ mt)
{
    const int row = blockIdx.x;
    const int b   = row >> 11;
    const int tid = threadIdx.x;
    const int lane = tid & 31, wid = tid >> 5;
    const float* x = logits + (size_t)row * V_;

    __shared__ float sh_e[V_];
    __shared__ float sh_g[S_];
    __shared__ float red[8];

    float v0 = x[tid];
    float v1 = x[tid + 256];
    float m = fmaxf(v0, v1);
    m = warpReduceMaxF(m);
    if (lane == 0) red[wid] = m;
    __syncthreads();
    float mm = red[0];
#pragma unroll
    for (int i = 1; i < 8; i++) mm = fmaxf(mm, red[i]);
    __syncthreads();

    float e0 = __expf(v0 - mm), e1 = __expf(v1 - mm);
    sh_e[tid] = e0;
    sh_e[tid + 256] = e1;
    float sm = warpReduceSumF(e0 + e1);
    if (lane == 0) red[wid] = sm;
    __syncthreads();
    float ssum = red[0];
#pragma unroll
    for (int i = 1; i < 8; i++) ssum += red[i];

    float lse = __logf(ssum);
    lp_out[(size_t)row * V_ + tid] = v0 - mm - lse;
    lp_out[(size_t)row * V_ + tid + 256] = v1 - mm - lse;

    float pm = 0.f;
    for (int s = tid; s < S_; s += 256) {
        int lab = (s & 1) ? targets[b * L_ + (s >> 1)] : 1;
        float p = sh_e[lab];
        sh_g[s] = p;
        pm = fmaxf(pm, p);
    }
    pm = warpReduceMaxF(pm);
    __syncthreads();
    if (lane == 0) red[wid] = pm;
    __syncthreads();
    float pmax = red[0];
#pragma unroll
    for (int i = 1; i < 8; i++) pmax = fmaxf(pmax, red[i]);
    float inv = 1.0f / pmax;
    for (int s = tid; s < S_; s += 256)
        Pext[(size_t)row * SP_ + s] = sh_g[s] * inv;
    if (tid == 0) mt[row] = __logf(pmax) - lse;
}

// -------------------- lengths ----------------------------------------------
__global__ __launch_bounds__(256) void lengths_kernel(
    const int* __restrict__ encm, const int* __restrict__ tgtm,
    float* __restrict__ out, int len_off, int loss_off,
    int* __restrict__ tlen, int* __restrict__ olen)
{
    const int b = blockIdx.x, tid = threadIdx.x;
    const int lane = tid & 31, wid = tid >> 5;
    int c1 = 0;
    for (int i = tid; i < SSRC; i += 256) c1 += (encm[b * SSRC + i] != 0);
    int c2 = 0;
    for (int i = tid; i < L_; i += 256) c2 += (tgtm[b * L_ + i] != 0);
    c1 = warpReduceSumI(c1);
    c2 = warpReduceSumI(c2);
    __shared__ int redi[16];
    if (lane == 0) { redi[wid] = c1; redi[8 + wid] = c2; }
    __syncthreads();
    if (tid == 0) {
        int a = 0, t = 0;
#pragma unroll
        for (int i = 0; i < 8; i++) { a += redi[i]; t += redi[8 + i]; }
        olen[b] = STR_ * a;
        tlen[b] = t;
        out[len_off + b] = (float)(STR_ * a);
        if (b == 0) out[loss_off] = 0.f;
    }
}

// -------------------- msum -------------------------------------------------
__global__ __launch_bounds__(256) void msum_kernel(
    const float* __restrict__ mt, const int* __restrict__ olen,
    float* __restrict__ Msum)
{
    const int b = blockIdx.x, tid = threadIdx.x;
    int il = olen[b]; if (il > T_) il = T_;
    float sacc = 0.f;
    for (int t = tid; t < il; t += 256) sacc += mt[b * T_ + t];
    sacc = warpReduceSumF(sacc);
    __shared__ float red[8];
    if ((tid & 31) == 0) red[tid >> 5] = sacc;
    __syncthreads();
    if (tid == 0) {
        float r = 0.f;
#pragma unroll
        for (int i = 0; i < 8; i++) r += red[i];
        Msum[b] = r;
    }
}

// -------------------- CTC forward DP (probability domain) ------------------
__global__ __launch_bounds__(544) void ctc_dp_kernel(
    const float* __restrict__ Pext, const float* __restrict__ Msum,
    const int* __restrict__ targets, const int* __restrict__ tlen,
    const int* __restrict__ olen, float* __restrict__ loss_slot)
{
    const int b = blockIdx.x;
    const int tid = threadIdx.x;
    __shared__ float sa[546];
    __shared__ __align__(16) float buf[2][CH_][SP_];
    __shared__ float warpred[17];
    __shared__ float s_inv;

    const int s = tid;
    const bool active = (s < S_);
    bool skip = false;
    if (active && (s & 1)) {
        int l = s >> 1;
        int tc = targets[b * L_ + l];
        bool ok = (tc != 1);
        if (l > 0) ok = ok && (tc != targets[b * L_ + l - 1]);
        skip = ok;
    }
    const int inlen = olen[b];
    const int tl = tlen[b];

    sa[tid] = 0.f;
    if (tid < 2) sa[544 + tid] = 0.f;

    const float* Pb = Pext + (size_t)b * T_ * SP_;
    const int li0 = tid, li1 = tid + 544;
    float4 r0 = make_float4(0.f, 0.f, 0.f, 0.f), r1 = r0;
    {
        const float4* src = (const float4*)Pb;
        if (li0 < 1040) r0 = src[li0];
        if (li1 < 1040) r1 = src[li1];
        float4* dst = (float4*)&buf[0][0][0];
        if (li0 < 1040) dst[li0] = r0;
        if (li1 < 1040) dst[li1] = r1;
    }
    __syncthreads();

    float Cacc = 0.f;
    for (int c = 0; c < NC_; c++) {
        if (c + 1 < NC_) {
            const float4* src = (const float4*)(Pb + (size_t)(c + 1) * CH_ * SP_);
            if (li0 < 1040) r0 = src[li0];
            if (li1 < 1040) r1 = src[li1];
        }
        const int cur = c & 1;
#pragma unroll
        for (int tr = 0; tr < CH_; tr++) {
            const int tg = c * CH_ + tr;
            float val = 0.f;
            if (active) {
                float P = buf[cur][tr][s];
                if (tg == 0) {
                    val = (s == 0 || (s == 1 && tl > 0)) ? P : 0.f;
                } else {
                    float a  = sa[2 + s];
                    float a1 = sa[1 + s];
                    float a2 = skip ? sa[s] : 0.f;
                    val = (a + a1 + a2) * P;
                }
            }
            __syncthreads();
            if (active && (tg == 0 || tg < inlen)) sa[2 + s] = val;
            __syncthreads();
        }
        if (c + 1 < NC_) {
            float4* dst = (float4*)&buf[cur ^ 1][0][0];
            if (li0 < 1040) dst[li0] = r0;
            if (li1 < 1040) dst[li1] = r1;
        }
        float mv = active ? sa[2 + s] : 0.f;
        mv = warpReduceMaxF(mv);
        if ((tid & 31) == 0) warpred[tid >> 5] = mv;
        __syncthreads();
        if (tid == 0) {
            float r = warpred[0];
#pragma unroll
            for (int i = 1; i < 17; i++) r = fmaxf(r, warpred[i]);
            if (r > 0.f) { s_inv = 1.0f / r; Cacc += __logf(r); }
            else s_inv = 1.0f;
        }
        __syncthreads();
        if (active) sa[2 + s] *= s_inv;
        __syncthreads();
    }

    if (tid == 0) {
        int il2 = 2 * tl;
        float al = sa[2 + il2];
        float ap = (tl > 0) ? sa[2 + il2 - 1] : 0.f;
        float per = -(__logf(al + ap) + Cacc + Msum[b]);
        float tld = (float)(tl > 0 ? tl : 1);
        atomicAdd(loss_slot, per / (tld * (float)B_));
    }
}

__global__ void finalize_kernel(float* out, int loss_off)
{
    float v = out[loss_off];
    if (!isfinite(v)) out[loss_off] = 0.f;
}

// -------------------- launch ------------------------------------------------
extern "C" void kernel_launch(void* const* d_in, const int* in_sizes, int n_in,
                              void* d_out, int out_size)
{
    const float* rep  = (const float*)d_in[0];
    const int*   encm = (const int*)d_in[1];
    const int*   tgt  = (const int*)d_in[2];
    const int*   tgtm = (const int*)d_in[3];
    const float* Wexp = (const float*)d_in[4];
    const float* bexp = (const float*)d_in[5];
    const float* W1   = (const float*)d_in[6];
    const float* b1   = (const float*)d_in[7];
    const float* W2   = (const float*)d_in[8];
    const float* b2   = (const float*)d_in[9];
    float* out = (float*)d_out;

    __nv_bfloat16 *p_reph, *p_repl, *p_Weth, *p_Wetl, *p_W1th, *p_W1tl, *p_W2th, *p_W2tl;
    __nv_bfloat16 *p_sth, *p_stl, *p_Hh, *p_Hl;
    float *p_logits, *p_Pext, *p_mt, *p_Msum;
    int *p_tlen, *p_olen;
    cudaGetSymbolAddress((void**)&p_reph, g_reph);
    cudaGetSymbolAddress((void**)&p_repl, g_repl);
    cudaGetSymbolAddress((void**)&p_Weth, g_Wexpt_h);
    cudaGetSymbolAddress((void**)&p_Wetl, g_Wexpt_l);
    cudaGetSymbolAddress((void**)&p_W1th, g_W1t_h);
    cudaGetSymbolAddress((void**)&p_W1tl, g_W1t_l);
    cudaGetSymbolAddress((void**)&p_W2th, g_W2t_h);
    cudaGetSymbolAddress((void**)&p_W2tl, g_W2t_l);
    cudaGetSymbolAddress((void**)&p_sth, g_sth);
    cudaGetSymbolAddress((void**)&p_stl, g_stl);
    cudaGetSymbolAddress((void**)&p_Hh, g_Hh);
    cudaGetSymbolAddress((void**)&p_Hl, g_Hl);
    cudaGetSymbolAddress((void**)&p_logits, g_logits);
    cudaGetSymbolAddress((void**)&p_Pext, g_Pext);
    cudaGetSymbolAddress((void**)&p_mt, g_mt);
    cudaGetSymbolAddress((void**)&p_Msum, g_Msum);
    cudaGetSymbolAddress((void**)&p_tlen, g_tlen);
    cudaGetSymbolAddress((void**)&p_olen, g_olen);

    const int SMEM_GEMM = 2 * 65536;
    cudaFuncSetAttribute(gemm_mma<false, false>, cudaFuncAttributeMaxDynamicSharedMemorySize, SMEM_GEMM);
    cudaFuncSetAttribute(gemm_mma<true,  false>, cudaFuncAttributeMaxDynamicSharedMemorySize, SMEM_GEMM);
    cudaFuncSetAttribute(gemm_mma<false, true >, cudaFuncAttributeMaxDynamicSharedMemorySize, SMEM_GEMM);

    // convert inputs to split-bf16
    conv_rep_kernel<<<8192, 256>>>(rep, p_reph, p_repl);
    wtrans_kernel<<<dim3(2048 / 32, 512 / 32), 256>>>(Wexp, p_Weth, p_Wetl, 512, 2048);
    wtrans_kernel<<<dim3(1024 / 32, 512 / 32), 256>>>(W1, p_W1th, p_W1tl, 512, 1024);
    wtrans_kernel<<<dim3(512 / 32, 1024 / 32), 256>>>(W2, p_W2th, p_W2tl, 1024, 512);

    // GEMM1: states[16384,2048] = rep @ Wexp + bexp
    gemm_mma<false, false><<<dim3(16, 128), 256, SMEM_GEMM>>>(
        p_reph, p_repl, p_Weth, p_Wetl, bexp, p_sth, p_stl, nullptr, 16384, 2048, 512);
    // GEMM2: H[65536,1024] = relu(states @ W1 + b1)
    gemm_mma<true, false><<<dim3(8, 512), 256, SMEM_GEMM>>>(
        p_sth, p_stl, p_W1th, p_W1tl, b1, p_Hh, p_Hl, nullptr, 65536, 1024, 512);
    // GEMM3: logits[65536,512] = H @ W2 + b2 (fp32 out)
    gemm_mma<false, true><<<dim3(4, 512), 256, SMEM_GEMM>>>(
        p_Hh, p_Hl, p_W2th, p_W2tl, b2, nullptr, nullptr, p_logits, 65536, 512, 1024);

    const int loss_off = out_size - 1;
    const int len_off  = out_size - 1 - B_;
    lengths_kernel<<<B_, 256>>>(encm, tgtm, out, len_off, loss_off, p_tlen, p_olen);
    softmax_gather_kernel<<<B_ * T_, 256>>>(p_logits, tgt, out, p_Pext, p_mt);
    msum_kernel<<<B_, 256>>>(p_mt, p_olen, p_Msum);
    ctc_dp_kernel<<<B_, 544>>>(p_Pext, p_Msum, tgt, p_tlen, p_olen, out + loss_off);
    finalize_kernel<<<1, 1>>>(out, loss_off);
}

// round 5
// speedup vs baseline: 2.6526x; 1.2345x over previous
#include <cuda_runtime.h>
#include <cuda_bf16.h>
#include <math.h>
#include <stdint.h>

// Problem constants
#define B_   32
#define SSRC 512
#define D_   512
#define STR_ 4
#define T_   2048
#define V_   512
#define L_   256
#define S_   513
#define SP_  520
#define CH_  8
#define NC_  (T_/CH_)

// -------------------- scratch (device globals) ----------------------------
__device__ __nv_bfloat16 g_reph[(size_t)16384 * 512];
__device__ __nv_bfloat16 g_repl[(size_t)16384 * 512];
__device__ __nv_bfloat16 g_Wexpt_h[(size_t)2048 * 512];
__device__ __nv_bfloat16 g_Wexpt_l[(size_t)2048 * 512];
__device__ __nv_bfloat16 g_W1t_h[(size_t)1024 * 512];
__device__ __nv_bfloat16 g_W1t_l[(size_t)1024 * 512];
__device__ __nv_bfloat16 g_W2t_h[(size_t)512 * 1024];
__device__ __nv_bfloat16 g_W2t_l[(size_t)512 * 1024];
__device__ __nv_bfloat16 g_sth[(size_t)16384 * 2048];  // states (bf16 hi only)
__device__ __nv_bfloat16 g_Hh[(size_t)65536 * 1024];   // hidden (bf16 hi only)
__device__ float g_logits[(size_t)65536 * 512];
__device__ float g_Pext[(size_t)B_ * T_ * SP_];
__device__ float g_mt[B_ * T_];
__device__ float g_Msum[B_];
__device__ int   g_tlen[B_];
__device__ int   g_olen[B_];

// -------------------- helpers ---------------------------------------------
__device__ __forceinline__ float warpReduceMaxF(float v) {
#pragma unroll
    for (int o = 16; o > 0; o >>= 1) v = fmaxf(v, __shfl_xor_sync(0xffffffffu, v, o));
    return v;
}
__device__ __forceinline__ float warpReduceSumF(float v) {
#pragma unroll
    for (int o = 16; o > 0; o >>= 1) v += __shfl_xor_sync(0xffffffffu, v, o);
    return v;
}
__device__ __forceinline__ int warpReduceSumI(int v) {
#pragma unroll
    for (int o = 16; o > 0; o >>= 1) v += __shfl_xor_sync(0xffffffffu, v, o);
    return v;
}
__device__ __forceinline__ unsigned short f2bf(float v) {
    __nv_bfloat16 h = __float2bfloat16(v);
    return *reinterpret_cast<unsigned short*>(&h);
}
__device__ __forceinline__ float bf2f(unsigned short u) {
    __nv_bfloat16 h = *reinterpret_cast<__nv_bfloat16*>(&u);
    return __bfloat162float(h);
}
__device__ __forceinline__ uint32_t smem_u32(const void* p) {
    uint32_t a;
    asm("{ .reg .u64 t; cvta.to.shared.u64 t, %1; cvt.u32.u64 %0, t; }" : "=r"(a) : "l"(p));
    return a;
}
__device__ __forceinline__ uint32_t swz128(uint32_t x) { return x ^ ((x >> 3) & 0x70u); }

__device__ __forceinline__ void cpa16(uint32_t dst, const void* src) {
    asm volatile("cp.async.cg.shared.global [%0], [%1], 16;" :: "r"(dst), "l"(src));
}
#define CP_COMMIT() asm volatile("cp.async.commit_group;" ::: "memory")
#define CP_WAIT0()  asm volatile("cp.async.wait_group 0;" ::: "memory")
#define CP_WAIT1()  asm volatile("cp.async.wait_group 1;" ::: "memory")

__device__ __forceinline__ void ldsm4(uint32_t* r, uint32_t a) {
    asm volatile("ldmatrix.sync.aligned.m8n8.x4.shared.b16 {%0,%1,%2,%3}, [%4];"
        : "=r"(r[0]), "=r"(r[1]), "=r"(r[2]), "=r"(r[3]) : "r"(a));
}
__device__ __forceinline__ void mma16816(float* c, const uint32_t* a, uint32_t b0, uint32_t b1) {
    asm volatile("mma.sync.aligned.m16n8k16.row.col.f32.bf16.bf16.f32 "
        "{%0,%1,%2,%3}, {%4,%5,%6,%7}, {%8,%9}, {%0,%1,%2,%3};"
        : "+f"(c[0]), "+f"(c[1]), "+f"(c[2]), "+f"(c[3])
        : "r"(a[0]), "r"(a[1]), "r"(a[2]), "r"(a[3]), "r"(b0), "r"(b1));
}

// -------------------- input conversion kernels -----------------------------
__global__ __launch_bounds__(256) void conv_rep_kernel(
    const float* __restrict__ x, __nv_bfloat16* __restrict__ h,
    __nv_bfloat16* __restrict__ l)
{
    int i = blockIdx.x * 256 + threadIdx.x;
    float4 v = ((const float4*)x)[i];
    ushort4 hs, ls;
    hs.x = f2bf(v.x); ls.x = f2bf(v.x - bf2f(hs.x));
    hs.y = f2bf(v.y); ls.y = f2bf(v.y - bf2f(hs.y));
    hs.z = f2bf(v.z); ls.z = f2bf(v.z - bf2f(hs.z));
    hs.w = f2bf(v.w); ls.w = f2bf(v.w - bf2f(hs.w));
    ((ushort4*)h)[i] = hs;
    ((ushort4*)l)[i] = ls;
}

// W [K,N] row-major -> T [N,K] bf16 hi/lo
__global__ __launch_bounds__(256) void wtrans_kernel(
    const float* __restrict__ W, __nv_bfloat16* __restrict__ Th,
    __nv_bfloat16* __restrict__ Tl, int K, int N)
{
    __shared__ float tile[32][33];
    const int bx = blockIdx.x, by = blockIdx.y;
    const int tx = threadIdx.x & 31, ty = threadIdx.x >> 5;
#pragma unroll
    for (int i = 0; i < 4; i++)
        tile[ty + i * 8][tx] = W[(size_t)(by * 32 + ty + i * 8) * N + bx * 32 + tx];
    __syncthreads();
#pragma unroll
    for (int i = 0; i < 4; i++) {
        float v = tile[tx][ty + i * 8];
        unsigned short h = f2bf(v);
        unsigned short lo = f2bf(v - bf2f(h));
        size_t o = (size_t)(bx * 32 + ty + i * 8) * K + by * 32 + tx;
        ((unsigned short*)Th)[o] = h;
        ((unsigned short*)Tl)[o] = lo;
    }
}

// -------------------- mma.sync split-bf16 GEMM -----------------------------
// NPROD=3: C = (Ah+Al)(Bh+Bl)^T ~ AhBh+AhBl+AlBh.  NPROD=2: C = Ah(Bh+Bl)^T.
// Block 128x128, K-chunk 64, 3-stage cp.async pipeline, 256 threads.
template <int NPROD, bool RELU, bool OUTF32>
__global__ __launch_bounds__(256) void gemm_mma(
    const __nv_bfloat16* __restrict__ Ah, const __nv_bfloat16* __restrict__ Al,
    const __nv_bfloat16* __restrict__ Bh, const __nv_bfloat16* __restrict__ Bl,
    const float* __restrict__ bias,
    __nv_bfloat16* __restrict__ Ch, float* __restrict__ Cf,
    int M, int N, int K)
{
    constexpr uint32_t OFF_BH = 16384, OFF_BL = 32768, OFF_AL = 49152;
    constexpr uint32_t STAGE = (NPROD == 3) ? 65536u : 49152u;
    extern __shared__ __align__(16) char dsm[];   // 3 stages
    const uint32_t sbase = smem_u32(dsm);
    const int tid = threadIdx.x;
    const int lane = tid & 31, w = tid >> 5;
    const int m0 = blockIdx.y * 128;
    const int n0 = blockIdx.x * 128;
    const int wm0 = (w >> 1) * 32;
    const int wn0 = (w & 1) * 64;
    const int nch = K >> 6;

    const int lrow = tid >> 3;        // 0..31
    const int lcg  = tid & 7;         // 16B group within 128B row
    const char* pAh = (const char*)Ah;
    const char* pAl = (const char*)Al;
    const char* pBh = (const char*)Bh;
    const char* pBl = (const char*)Bl;

#define ISSUE(k0, sb_)                                                         \
    {                                                                          \
        uint32_t sb = (sb_);                                                   \
        _Pragma("unroll")                                                      \
        for (int j = 0; j < 4; j++) {                                          \
            int r = lrow + j * 32;                                             \
            uint32_t so = swz128((uint32_t)(r * 128 + lcg * 16));              \
            size_t goA = ((size_t)(m0 + r) * K + (k0) + lcg * 8) * 2;          \
            size_t goB = ((size_t)(n0 + r) * K + (k0) + lcg * 8) * 2;          \
            cpa16(sb + so, pAh + goA);                                         \
            cpa16(sb + OFF_BH + so, pBh + goB);                                \
            cpa16(sb + OFF_BL + so, pBl + goB);                                \
            if (NPROD == 3) cpa16(sb + OFF_AL + so, pAl + goA);                \
        }                                                                      \
    }

    float acc[2][8][4];
#pragma unroll
    for (int mt = 0; mt < 2; mt++)
#pragma unroll
        for (int nt = 0; nt < 8; nt++)
#pragma unroll
            for (int q = 0; q < 4; q++) acc[mt][nt][q] = 0.f;

    const uint32_t stg[3] = {sbase, sbase + STAGE, sbase + 2 * STAGE};

    ISSUE(0, stg[0]); CP_COMMIT();
    ISSUE(64, stg[1]); CP_COMMIT();

    const int rl = ((lane >> 3) & 1) * 8 + (lane & 7);
    const int kb = (lane >> 4) * 8;

    int cs = 0;      // compute stage
    int is2 = 2;     // stage for chunk c+2
#pragma unroll 1
    for (int c = 0; c < nch; c++) {
        if (c == nch - 1) { CP_WAIT0(); } else { CP_WAIT1(); }
        __syncthreads();
        if (c + 2 < nch) {
            ISSUE((c + 2) << 6, stg[is2]); CP_COMMIT();
            if (++is2 == 3) is2 = 0;
        }

        const uint32_t ah_b = stg[cs];
        const uint32_t bh_b = ah_b + OFF_BH;
        const uint32_t bl_b = ah_b + OFF_BL;
        const uint32_t al_b = ah_b + OFF_AL;
        if (++cs == 3) cs = 0;
#pragma unroll
        for (int ks = 0; ks < 4; ks++) {
            const uint32_t kof = (uint32_t)((ks * 16 + kb) * 2);
            uint32_t aH[2][4], aL[2][4];
#pragma unroll
            for (int mt = 0; mt < 2; mt++) {
                uint32_t off = swz128((uint32_t)((wm0 + mt * 16 + rl) * 128) + kof);
                ldsm4(aH[mt], ah_b + off);
                if (NPROD == 3) ldsm4(aL[mt], al_b + off);
            }
            uint32_t bH[4][4], bL[4][4];
#pragma unroll
            for (int ng = 0; ng < 4; ng++) {
                uint32_t off = swz128((uint32_t)((wn0 + ng * 16 + rl) * 128) + kof);
                ldsm4(bH[ng], bh_b + off);
                ldsm4(bL[ng], bl_b + off);
            }
#pragma unroll
            for (int mt = 0; mt < 2; mt++)
#pragma unroll
                for (int nt = 0; nt < 8; nt++) {
                    const int ng = nt >> 1, sl = nt & 1;
                    mma16816(acc[mt][nt], aH[mt], bH[ng][sl], bH[ng][sl + 2]);
                    mma16816(acc[mt][nt], aH[mt], bL[ng][sl], bL[ng][sl + 2]);
                    if (NPROD == 3)
                        mma16816(acc[mt][nt], aL[mt], bH[ng][sl], bH[ng][sl + 2]);
                }
        }
    }

    // epilogue (bf16-hi or f32 out)
#pragma unroll
    for (int mt = 0; mt < 2; mt++) {
#pragma unroll
        for (int nt = 0; nt < 8; nt++) {
            const int row = m0 + wm0 + mt * 16 + (lane >> 2);
            const int col = n0 + wn0 + nt * 8 + (lane & 3) * 2;
            float bv0 = __ldg(bias + col);
            float bv1 = __ldg(bias + col + 1);
            float v00 = acc[mt][nt][0] + bv0;
            float v01 = acc[mt][nt][1] + bv1;
            float v10 = acc[mt][nt][2] + bv0;
            float v11 = acc[mt][nt][3] + bv1;
            if (RELU) {
                v00 = fmaxf(v00, 0.f); v01 = fmaxf(v01, 0.f);
                v10 = fmaxf(v10, 0.f); v11 = fmaxf(v11, 0.f);
            }
            size_t g0 = (size_t)row * N + col;
            size_t g1 = (size_t)(row + 8) * N + col;
            if (OUTF32) {
                *(float2*)(Cf + g0) = make_float2(v00, v01);
                *(float2*)(Cf + g1) = make_float2(v10, v11);
            } else {
                ushort2 h0, h1;
                h0.x = f2bf(v00); h0.y = f2bf(v01);
                h1.x = f2bf(v10); h1.y = f2bf(v11);
                *(ushort2*)((unsigned short*)Ch + g0) = h0;
                *(ushort2*)((unsigned short*)Ch + g1) = h1;
            }
        }
    }
#undef ISSUE
}

// -------------------- fused log-softmax + label gather ---------------------
__global__ __launch_bounds__(256) void softmax_gather_kernel(
    const float* __restrict__ logits, const int* __restrict__ targets,
    float* __restrict__ lp_out, float* __restrict__ Pext, float* __restrict__ mt)
{
    const int row = blockIdx.x;
    const int b   = row >> 11;
    const int tid = threadIdx.x;
    const int lane = tid & 31, wid = tid >> 5;
    const float* x = logits + (size_t)row * V_;

    __shared__ float sh_e[V_];
    __shared__ float sh_g[S_];
    __shared__ float red[8];

    float v0 = x[tid];
    float v1 = x[tid + 256];
    float m = fmaxf(v0, v1);
    m = warpReduceMaxF(m);
    if (lane == 0) red[wid] = m;
    __syncthreads();
    float mm = red[0];
#pragma unroll
    for (int i = 1; i < 8; i++) mm = fmaxf(mm, red[i]);
    __syncthreads();

    float e0 = __expf(v0 - mm), e1 = __expf(v1 - mm);
    sh_e[tid] = e0;
    sh_e[tid + 256] = e1;
    float sm = warpReduceSumF(e0 + e1);
    if (lane == 0) red[wid] = sm;
    __syncthreads();
    float ssum = red[0];
#pragma unroll
    for (int i = 1; i < 8; i++) ssum += red[i];

    float lse = __logf(ssum);
    lp_out[(size_t)row * V_ + tid] = v0 - mm - lse;
    lp_out[(size_t)row * V_ + tid + 256] = v1 - mm - lse;

    float pm = 0.f;
    for (int s = tid; s < S_; s += 256) {
        int lab = (s & 1) ? targets[b * L_ + (s >> 1)] : 1;
        float p = sh_e[lab];
        sh_g[s] = p;
        pm = fmaxf(pm, p);
    }
    pm = warpReduceMaxF(pm);
    __syncthreads();
    if (lane == 0) red[wid] = pm;
    __syncthreads();
    float pmax = red[0];
#pragma unroll
    for (int i = 1; i < 8; i++) pmax = fmaxf(pmax, red[i]);
    float inv = 1.0f / pmax;
    for (int s = tid; s < S_; s += 256)
        Pext[(size_t)row * SP_ + s] = sh_g[s] * inv;
    if (tid == 0) mt[row] = __logf(pmax) - lse;
}

// -------------------- lengths ----------------------------------------------
__global__ __launch_bounds__(256) void lengths_kernel(
    const int* __restrict__ encm, const int* __restrict__ tgtm,
    float* __restrict__ out, int len_off, int loss_off,
    int* __restrict__ tlen, int* __restrict__ olen)
{
    const int b = blockIdx.x, tid = threadIdx.x;
    const int lane = tid & 31, wid = tid >> 5;
    int c1 = 0;
    for (int i = tid; i < SSRC; i += 256) c1 += (encm[b * SSRC + i] != 0);
    int c2 = 0;
    for (int i = tid; i < L_; i += 256) c2 += (tgtm[b * L_ + i] != 0);
    c1 = warpReduceSumI(c1);
    c2 = warpReduceSumI(c2);
    __shared__ int redi[16];
    if (lane == 0) { redi[wid] = c1; redi[8 + wid] = c2; }
    __syncthreads();
    if (tid == 0) {
        int a = 0, t = 0;
#pragma unroll
        for (int i = 0; i < 8; i++) { a += redi[i]; t += redi[8 + i]; }
        olen[b] = STR_ * a;
        tlen[b] = t;
        out[len_off + b] = (float)(STR_ * a);
        if (b == 0) out[loss_off] = 0.f;
    }
}

// -------------------- msum -------------------------------------------------
__global__ __launch_bounds__(256) void msum_kernel(
    const float* __restrict__ mt, const int* __restrict__ olen,
    float* __restrict__ Msum)
{
    const int b = blockIdx.x, tid = threadIdx.x;
    int il = olen[b]; if (il > T_) il = T_;
    float sacc = 0.f;
    for (int t = tid; t < il; t += 256) sacc += mt[b * T_ + t];
    sacc = warpReduceSumF(sacc);
    __shared__ float red[8];
    if ((tid & 31) == 0) red[tid >> 5] = sacc;
    __syncthreads();
    if (tid == 0) {
        float r = 0.f;
#pragma unroll
        for (int i = 0; i < 8; i++) r += red[i];
        Msum[b] = r;
    }
}

// -------------------- CTC forward DP (probability domain) ------------------
__global__ __launch_bounds__(544) void ctc_dp_kernel(
    const float* __restrict__ Pext, const float* __restrict__ Msum,
    const int* __restrict__ targets, const int* __restrict__ tlen,
    const int* __restrict__ olen, float* __restrict__ loss_slot)
{
    const int b = blockIdx.x;
    const int tid = threadIdx.x;
    __shared__ float sa[546];
    __shared__ __align__(16) float buf[2][CH_][SP_];
    __shared__ float warpred[17];
    __shared__ float s_inv;

    const int s = tid;
    const bool active = (s < S_);
    bool skip = false;
    if (active && (s & 1)) {
        int l = s >> 1;
        int tc = targets[b * L_ + l];
        bool ok = (tc != 1);
        if (l > 0) ok = ok && (tc != targets[b * L_ + l - 1]);
        skip = ok;
    }
    const int inlen = olen[b];
    const int tl = tlen[b];

    sa[tid] = 0.f;
    if (tid < 2) sa[544 + tid] = 0.f;

    const float* Pb = Pext + (size_t)b * T_ * SP_;
    const int li0 = tid, li1 = tid + 544;
    float4 r0 = make_float4(0.f, 0.f, 0.f, 0.f), r1 = r0;
    {
        const float4* src = (const float4*)Pb;
        if (li0 < 1040) r0 = src[li0];
        if (li1 < 1040) r1 = src[li1];
        float4* dst = (float4*)&buf[0][0][0];
        if (li0 < 1040) dst[li0] = r0;
        if (li1 < 1040) dst[li1] = r1;
    }
    __syncthreads();

    float Cacc = 0.f;
    for (int c = 0; c < NC_; c++) {
        if (c + 1 < NC_) {
            const float4* src = (const float4*)(Pb + (size_t)(c + 1) * CH_ * SP_);
            if (li0 < 1040) r0 = src[li0];
            if (li1 < 1040) r1 = src[li1];
        }
        const int cur = c & 1;
#pragma unroll
        for (int tr = 0; tr < CH_; tr++) {
            const int tg = c * CH_ + tr;
            float val = 0.f;
            if (active) {
                float P = buf[cur][tr][s];
                if (tg == 0) {
                    val = (s == 0 || (s == 1 && tl > 0)) ? P : 0.f;
                } else {
                    float a  = sa[2 + s];
                    float a1 = sa[1 + s];
                    float a2 = skip ? sa[s] : 0.f;
                    val = (a + a1 + a2) * P;
                }
            }
            __syncthreads();
            if (active && (tg == 0 || tg < inlen)) sa[2 + s] = val;
            __syncthreads();
        }
        if (c + 1 < NC_) {
            float4* dst = (float4*)&buf[cur ^ 1][0][0];
            if (li0 < 1040) dst[li0] = r0;
            if (li1 < 1040) dst[li1] = r1;
        }
        float mv = active ? sa[2 + s] : 0.f;
        mv = warpReduceMaxF(mv);
        if ((tid & 31) == 0) warpred[tid >> 5] = mv;
        __syncthreads();
        if (tid == 0) {
            float r = warpred[0];
#pragma unroll
            for (int i = 1; i < 17; i++) r = fmaxf(r, warpred[i]);
            if (r > 0.f) { s_inv = 1.0f / r; Cacc += __logf(r); }
            else s_inv = 1.0f;
        }
        __syncthreads();
        if (active) sa[2 + s] *= s_inv;
        __syncthreads();
    }

    if (tid == 0) {
        int il2 = 2 * tl;
        float al = sa[2 + il2];
        float ap = (tl > 0) ? sa[2 + il2 - 1] : 0.f;
        float per = -(__logf(al + ap) + Cacc + Msum[b]);
        float tld = (float)(tl > 0 ? tl : 1);
        atomicAdd(loss_slot, per / (tld * (float)B_));
    }
}

__global__ void finalize_kernel(float* out, int loss_off)
{
    float v = out[loss_off];
    if (!isfinite(v)) out[loss_off] = 0.f;
}

// -------------------- launch ------------------------------------------------
extern "C" void kernel_launch(void* const* d_in, const int* in_sizes, int n_in,
                              void* d_out, int out_size)
{
    const float* rep  = (const float*)d_in[0];
    const int*   encm = (const int*)d_in[1];
    const int*   tgt  = (const int*)d_in[2];
    const int*   tgtm = (const int*)d_in[3];
    const float* Wexp = (const float*)d_in[4];
    const float* bexp = (const float*)d_in[5];
    const float* W1   = (const float*)d_in[6];
    const float* b1   = (const float*)d_in[7];
    const float* W2   = (const float*)d_in[8];
    const float* b2   = (const float*)d_in[9];
    float* out = (float*)d_out;

    __nv_bfloat16 *p_reph, *p_repl, *p_Weth, *p_Wetl, *p_W1th, *p_W1tl, *p_W2th, *p_W2tl;
    __nv_bfloat16 *p_sth, *p_Hh;
    float *p_logits, *p_Pext, *p_mt, *p_Msum;
    int *p_tlen, *p_olen;
    cudaGetSymbolAddress((void**)&p_reph, g_reph);
    cudaGetSymbolAddress((void**)&p_repl, g_repl);
    cudaGetSymbolAddress((void**)&p_Weth, g_Wexpt_h);
    cudaGetSymbolAddress((void**)&p_Wetl, g_Wexpt_l);
    cudaGetSymbolAddress((void**)&p_W1th, g_W1t_h);
    cudaGetSymbolAddress((void**)&p_W1tl, g_W1t_l);
    cudaGetSymbolAddress((void**)&p_W2th, g_W2t_h);
    cudaGetSymbolAddress((void**)&p_W2tl, g_W2t_l);
    cudaGetSymbolAddress((void**)&p_sth, g_sth);
    cudaGetSymbolAddress((void**)&p_Hh, g_Hh);
    cudaGetSymbolAddress((void**)&p_logits, g_logits);
    cudaGetSymbolAddress((void**)&p_Pext, g_Pext);
    cudaGetSymbolAddress((void**)&p_mt, g_mt);
    cudaGetSymbolAddress((void**)&p_Msum, g_Msum);
    cudaGetSymbolAddress((void**)&p_tlen, g_tlen);
    cudaGetSymbolAddress((void**)&p_olen, g_olen);

    const int SMEM3 = 3 * 65536;   // NPROD=3
    const int SMEM2 = 3 * 49152;   // NPROD=2
    cudaFuncSetAttribute(gemm_mma<3, false, false>, cudaFuncAttributeMaxDynamicSharedMemorySize, SMEM3);
    cudaFuncSetAttribute(gemm_mma<2, true,  false>, cudaFuncAttributeMaxDynamicSharedMemorySize, SMEM2);
    cudaFuncSetAttribute(gemm_mma<2, false, true >, cudaFuncAttributeMaxDynamicSharedMemorySize, SMEM2);

    // convert inputs to split-bf16
    conv_rep_kernel<<<8192, 256>>>(rep, p_reph, p_repl);
    wtrans_kernel<<<dim3(2048 / 32, 512 / 32), 256>>>(Wexp, p_Weth, p_Wetl, 512, 2048);
    wtrans_kernel<<<dim3(1024 / 32, 512 / 32), 256>>>(W1, p_W1th, p_W1tl, 512, 1024);
    wtrans_kernel<<<dim3(512 / 32, 1024 / 32), 256>>>(W2, p_W2th, p_W2tl, 1024, 512);

    // GEMM1: states[16384,2048] = rep @ Wexp + bexp  (3-product, bf16-hi out)
    gemm_mma<3, false, false><<<dim3(16, 128), 256, SMEM3>>>(
        p_reph, p_repl, p_Weth, p_Wetl, bexp, p_sth, nullptr, 16384, 2048, 512);
    // GEMM2: H[65536,1024] = relu(states @ W1 + b1)  (2-product, bf16-hi out)
    gemm_mma<2, true, false><<<dim3(8, 512), 256, SMEM2>>>(
        p_sth, nullptr, p_W1th, p_W1tl, b1, p_Hh, nullptr, 65536, 1024, 512);
    // GEMM3: logits[65536,512] = H @ W2 + b2  (2-product, fp32 out)
    gemm_mma<2, false, true><<<dim3(4, 512), 256, SMEM2>>>(
        p_Hh, nullptr, p_W2th, p_W2tl, b2, nullptr, p_logits, 65536, 512, 1024);

    const int loss_off = out_size - 1;
    const int len_off  = out_size - 1 - B_;
    lengths_kernel<<<B_, 256>>>(encm, tgtm, out, len_off, loss_off, p_tlen, p_olen);
    softmax_gather_kernel<<<B_ * T_, 256>>>(p_logits, tgt, out, p_Pext, p_mt);
    msum_kernel<<<B_, 256>>>(p_mt, p_olen, p_Msum);
    ctc_dp_kernel<<<B_, 544>>>(p_Pext, p_Msum, tgt, p_tlen, p_olen, out + loss_off);
    finalize_kernel<<<1, 1>>>(out, loss_off);
}

// round 7
// speedup vs baseline: 4.2220x; 1.5916x over previous
#include <cuda_runtime.h>
#include <cuda_fp16.h>
#include <math.h>
#include <stdint.h>

// Problem constants
#define B_   32
#define SSRC 512
#define D_   512
#define STR_ 4
#define T_   2048
#define V_   512
#define L_   256
#define S_   513
#define SP_  520
#define CH_  8
#define NC_  (T_/CH_)

// -------------------- scratch (device globals) ----------------------------
__device__ __half g_repf[(size_t)16384 * 512];
__device__ __half g_Wexpt[(size_t)2048 * 512];
__device__ __half g_W1t[(size_t)1024 * 512];
__device__ __half g_W2t[(size_t)512 * 1024];
__device__ __half g_st[(size_t)16384 * 2048];    // states fp16
__device__ __half g_H[(size_t)65536 * 1024];     // hidden fp16
__device__ float g_logits[(size_t)65536 * 512];
__device__ float g_Pext[(size_t)B_ * T_ * SP_];
__device__ float g_mt[B_ * T_];
__device__ float g_Msum[B_];
__device__ int   g_tlen[B_];
__device__ int   g_olen[B_];

// -------------------- helpers ---------------------------------------------
__device__ __forceinline__ float warpReduceMaxF(float v) {
#pragma unroll
    for (int o = 16; o > 0; o >>= 1) v = fmaxf(v, __shfl_xor_sync(0xffffffffu, v, o));
    return v;
}
__device__ __forceinline__ float warpReduceSumF(float v) {
#pragma unroll
    for (int o = 16; o > 0; o >>= 1) v += __shfl_xor_sync(0xffffffffu, v, o);
    return v;
}
__device__ __forceinline__ int warpReduceSumI(int v) {
#pragma unroll
    for (int o = 16; o > 0; o >>= 1) v += __shfl_xor_sync(0xffffffffu, v, o);
    return v;
}
__device__ __forceinline__ uint32_t smem_u32(const void* p) {
    uint32_t a;
    asm("{ .reg .u64 t; cvta.to.shared.u64 t, %1; cvt.u32.u64 %0, t; }" : "=r"(a) : "l"(p));
    return a;
}
__device__ __forceinline__ uint32_t swz128(uint32_t x) { return x ^ ((x >> 3) & 0x70u); }

__device__ __forceinline__ void cpa16(uint32_t dst, const void* src) {
    asm volatile("cp.async.cg.shared.global [%0], [%1], 16;" :: "r"(dst), "l"(src));
}
#define CP_COMMIT() asm volatile("cp.async.commit_group;" ::: "memory")
#define CP_WAIT0()  asm volatile("cp.async.wait_group 0;" ::: "memory")
#define CP_WAIT1()  asm volatile("cp.async.wait_group 1;" ::: "memory")

__device__ __forceinline__ void ldsm4(uint32_t* r, uint32_t a) {
    asm volatile("ldmatrix.sync.aligned.m8n8.x4.shared.b16 {%0,%1,%2,%3}, [%4];"
        : "=r"(r[0]), "=r"(r[1]), "=r"(r[2]), "=r"(r[3]) : "r"(a));
}
__device__ __forceinline__ void mma16816(float* c, const uint32_t* a, uint32_t b0, uint32_t b1) {
    asm volatile("mma.sync.aligned.m16n8k16.row.col.f32.f16.f16.f32 "
        "{%0,%1,%2,%3}, {%4,%5,%6,%7}, {%8,%9}, {%0,%1,%2,%3};"
        : "+f"(c[0]), "+f"(c[1]), "+f"(c[2]), "+f"(c[3])
        : "r"(a[0]), "r"(a[1]), "r"(a[2]), "r"(a[3]), "r"(b0), "r"(b1));
}

// -------------------- input conversion kernels -----------------------------
__global__ __launch_bounds__(256) void conv_rep_kernel(
    const float* __restrict__ x, __half* __restrict__ h)
{
    int i = blockIdx.x * 256 + threadIdx.x;
    float4 v = ((const float4*)x)[i];
    __half2 h01 = __floats2half2_rn(v.x, v.y);
    __half2 h23 = __floats2half2_rn(v.z, v.w);
    ((__half2*)h)[2 * i]     = h01;
    ((__half2*)h)[2 * i + 1] = h23;
}

// W [K,N] row-major -> T [N,K] fp16
__global__ __launch_bounds__(256) void wtrans_kernel(
    const float* __restrict__ W, __half* __restrict__ Th, int K, int N)
{
    __shared__ float tile[32][33];
    const int bx = blockIdx.x, by = blockIdx.y;
    const int tx = threadIdx.x & 31, ty = threadIdx.x >> 5;
#pragma unroll
    for (int i = 0; i < 4; i++)
        tile[ty + i * 8][tx] = W[(size_t)(by * 32 + ty + i * 8) * N + bx * 32 + tx];
    __syncthreads();
#pragma unroll
    for (int i = 0; i < 4; i++) {
        float v = tile[tx][ty + i * 8];
        size_t o = (size_t)(bx * 32 + ty + i * 8) * K + by * 32 + tx;
        Th[o] = __float2half_rn(v);
    }
}

// -------------------- fp16 mma.sync GEMM -----------------------------------
// C[M,N] = A[M,K] @ B[N,K]^T + bias.  Block 128x128, K-chunk 64,
// 3-stage cp.async pipeline, 256 threads, target occupancy 2.
template <bool RELU, bool OUTF32>
__global__ __launch_bounds__(256, 2) void gemm_f16(
    const __half* __restrict__ A, const __half* __restrict__ Bw,
    const float* __restrict__ bias,
    __half* __restrict__ Ch, float* __restrict__ Cf,
    int M, int N, int K)
{
    constexpr uint32_t OFF_B = 16384;
    constexpr uint32_t STAGE = 32768;
    extern __shared__ __align__(16) char dsm[];   // 3 stages x 32 KB
    const uint32_t sbase = smem_u32(dsm);
    const int tid = threadIdx.x;
    const int lane = tid & 31, w = tid >> 5;
    const int m0 = blockIdx.y * 128;
    const int n0 = blockIdx.x * 128;
    const int wm0 = (w >> 1) * 32;
    const int wn0 = (w & 1) * 64;
    const int nch = K >> 6;

    const int lrow = tid >> 3;        // 0..31
    const int lcg  = tid & 7;         // 16B group within 128B row
    const char* pA = (const char*)A;
    const char* pB = (const char*)Bw;

#define ISSUE(k0, sb_)                                                         \
    {                                                                          \
        uint32_t sb = (sb_);                                                   \
        _Pragma("unroll")                                                      \
        for (int j = 0; j < 4; j++) {                                          \
            int r = lrow + j * 32;                                             \
            uint32_t so = swz128((uint32_t)(r * 128 + lcg * 16));              \
            size_t goA = ((size_t)(m0 + r) * K + (k0) + lcg * 8) * 2;          \
            size_t goB = ((size_t)(n0 + r) * K + (k0) + lcg * 8) * 2;          \
            cpa16(sb + so, pA + goA);                                          \
            cpa16(sb + OFF_B + so, pB + goB);                                  \
        }                                                                      \
    }

    float acc[2][8][4];
#pragma unroll
    for (int mt = 0; mt < 2; mt++)
#pragma unroll
        for (int nt = 0; nt < 8; nt++)
#pragma unroll
            for (int q = 0; q < 4; q++) acc[mt][nt][q] = 0.f;

    const uint32_t stg[3] = {sbase, sbase + STAGE, sbase + 2 * STAGE};

    ISSUE(0, stg[0]); CP_COMMIT();
    ISSUE(64, stg[1]); CP_COMMIT();

    const int rl = ((lane >> 3) & 1) * 8 + (lane & 7);
    const int kb = (lane >> 4) * 8;

    int cs = 0;      // compute stage
    int is2 = 2;     // stage for chunk c+2
#pragma unroll 1
    for (int c = 0; c < nch; c++) {
        if (c == nch - 1) { CP_WAIT0(); } else { CP_WAIT1(); }
        __syncthreads();
        if (c + 2 < nch) {
            ISSUE((c + 2) << 6, stg[is2]); CP_COMMIT();
            if (++is2 == 3) is2 = 0;
        }

        const uint32_t a_b = stg[cs];
        const uint32_t b_b = a_b + OFF_B;
        if (++cs == 3) cs = 0;
#pragma unroll
        for (int ks = 0; ks < 4; ks++) {
            const uint32_t kof = (uint32_t)((ks * 16 + kb) * 2);
            uint32_t aH[2][4];
#pragma unroll
            for (int mt = 0; mt < 2; mt++) {
                uint32_t off = swz128((uint32_t)((wm0 + mt * 16 + rl) * 128) + kof);
                ldsm4(aH[mt], a_b + off);
            }
            uint32_t bH[4][4];
#pragma unroll
            for (int ng = 0; ng < 4; ng++) {
                uint32_t off = swz128((uint32_t)((wn0 + ng * 16 + rl) * 128) + kof);
                ldsm4(bH[ng], b_b + off);
            }
#pragma unroll
            for (int mt = 0; mt < 2; mt++)
#pragma unroll
                for (int nt = 0; nt < 8; nt++) {
                    const int ng = nt >> 1, sl = nt & 1;
                    mma16816(acc[mt][nt], aH[mt], bH[ng][sl], bH[ng][sl + 2]);
                }
        }
    }

    // epilogue (fp16 or f32 out)
#pragma unroll
    for (int mt = 0; mt < 2; mt++) {
#pragma unroll
        for (int nt = 0; nt < 8; nt++) {
            const int row = m0 + wm0 + mt * 16 + (lane >> 2);
            const int col = n0 + wn0 + nt * 8 + (lane & 3) * 2;
            float bv0 = __ldg(bias + col);
            float bv1 = __ldg(bias + col + 1);
            float v00 = acc[mt][nt][0] + bv0;
            float v01 = acc[mt][nt][1] + bv1;
            float v10 = acc[mt][nt][2] + bv0;
            float v11 = acc[mt][nt][3] + bv1;
            if (RELU) {
                v00 = fmaxf(v00, 0.f); v01 = fmaxf(v01, 0.f);
                v10 = fmaxf(v10, 0.f); v11 = fmaxf(v11, 0.f);
            }
            size_t g0 = (size_t)row * N + col;
            size_t g1 = (size_t)(row + 8) * N + col;
            if (OUTF32) {
                *(float2*)(Cf + g0) = make_float2(v00, v01);
                *(float2*)(Cf + g1) = make_float2(v10, v11);
            } else {
                *(__half2*)(Ch + g0) = __floats2half2_rn(v00, v01);
                *(__half2*)(Ch + g1) = __floats2half2_rn(v10, v11);
            }
        }
    }
#undef ISSUE
}

// -------------------- fused log-softmax + label gather ---------------------
__global__ __launch_bounds__(256) void softmax_gather_kernel(
    const float* __restrict__ logits, const int* __restrict__ targets,
    float* __restrict__ lp_out, float* __restrict__ Pext, float* __restrict__ mt)
{
    const int row = blockIdx.x;
    const int b   = row >> 11;
    const int tid = threadIdx.x;
    const int lane = tid & 31, wid = tid >> 5;
    const float* x = logits + (size_t)row * V_;

    __shared__ float sh_e[V_];
    __shared__ float sh_g[S_];
    __shared__ float red[8];

    float v0 = x[tid];
    float v1 = x[tid + 256];
    float m = fmaxf(v0, v1);
    m = warpReduceMaxF(m);
    if (lane == 0) red[wid] = m;
    __syncthreads();
    float mm = red[0];
#pragma unroll
    for (int i = 1; i < 8; i++) mm = fmaxf(mm, red[i]);
    __syncthreads();

    float e0 = __expf(v0 - mm), e1 = __expf(v1 - mm);
    sh_e[tid] = e0;
    sh_e[tid + 256] = e1;
    float sm = warpReduceSumF(e0 + e1);
    if (lane == 0) red[wid] = sm;
    __syncthreads();
    float ssum = red[0];
#pragma unroll
    for (int i = 1; i < 8; i++) ssum += red[i];

    float lse = __logf(ssum);
    lp_out[(size_t)row * V_ + tid] = v0 - mm - lse;
    lp_out[(size_t)row * V_ + tid + 256] = v1 - mm - lse;

    float pm = 0.f;
    for (int s = tid; s < S_; s += 256) {
        int lab = (s & 1) ? targets[b * L_ + (s >> 1)] : 1;
        float p = sh_e[lab];
        sh_g[s] = p;
        pm = fmaxf(pm, p);
    }
    pm = warpReduceMaxF(pm);
    __syncthreads();
    if (lane == 0) red[wid] = pm;
    __syncthreads();
    float pmax = red[0];
#pragma unroll
    for (int i = 1; i < 8; i++) pmax = fmaxf(pmax, red[i]);
    float inv = 1.0f / pmax;
    for (int s = tid; s < S_; s += 256)
        Pext[(size_t)row * SP_ + s] = sh_g[s] * inv;
    if (tid == 0) mt[row] = __logf(pmax) - lse;
}

// -------------------- lengths ----------------------------------------------
__global__ __launch_bounds__(256) void lengths_kernel(
    const int* __restrict__ encm, const int* __restrict__ tgtm,
    float* __restrict__ out, int len_off, int loss_off,
    int* __restrict__ tlen, int* __restrict__ olen)
{
    const int b = blockIdx.x, tid = threadIdx.x;
    const int lane = tid & 31, wid = tid >> 5;
    int c1 = 0;
    for (int i = tid; i < SSRC; i += 256) c1 += (encm[b * SSRC + i] != 0);
    int c2 = 0;
    for (int i = tid; i < L_; i += 256) c2 += (tgtm[b * L_ + i] != 0);
    c1 = warpReduceSumI(c1);
    c2 = warpReduceSumI(c2);
    __shared__ int redi[16];
    if (lane == 0) { redi[wid] = c1; redi[8 + wid] = c2; }
    __syncthreads();
    if (tid == 0) {
        int a = 0, t = 0;
#pragma unroll
        for (int i = 0; i < 8; i++) { a += redi[i]; t += redi[8 + i]; }
        olen[b] = STR_ * a;
        tlen[b] = t;
        out[len_off + b] = (float)(STR_ * a);
        if (b == 0) out[loss_off] = 0.f;
    }
}

// -------------------- msum -------------------------------------------------
__global__ __launch_bounds__(256) void msum_kernel(
    const float* __restrict__ mt, const int* __restrict__ olen,
    float* __restrict__ Msum)
{
    const int b = blockIdx.x, tid = threadIdx.x;
    int il = olen[b]; if (il > T_) il = T_;
    float sacc = 0.f;
    for (int t = tid; t < il; t += 256) sacc += mt[b * T_ + t];
    sacc = warpReduceSumF(sacc);
    __shared__ float red[8];
    if ((tid & 31) == 0) red[tid >> 5] = sacc;
    __syncthreads();
    if (tid == 0) {
        float r = 0.f;
#pragma unroll
        for (int i = 0; i < 8; i++) r += red[i];
        Msum[b] = r;
    }
}

// -------------------- CTC forward DP (probability domain) ------------------
__global__ __launch_bounds__(544) void ctc_dp_kernel(
    const float* __restrict__ Pext, const float* __restrict__ Msum,
    const int* __restrict__ targets, const int* __restrict__ tlen,
    const int* __restrict__ olen, float* __restrict__ loss_slot)
{
    const int b = blockIdx.x;
    const int tid = threadIdx.x;
    __shared__ float sa[546];
    __shared__ __align__(16) float buf[2][CH_][SP_];
    __shared__ float warpred[17];
    __shared__ float s_inv;

    const int s = tid;
    const bool active = (s < S_);
    bool skip = false;
    if (active && (s & 1)) {
        int l = s >> 1;
        int tc = targets[b * L_ + l];
        bool ok = (tc != 1);
        if (l > 0) ok = ok && (tc != targets[b * L_ + l - 1]);
        skip = ok;
    }
    const int inlen = olen[b];
    const int tl = tlen[b];

    sa[tid] = 0.f;
    if (tid < 2) sa[544 + tid] = 0.f;

    const float* Pb = Pext + (size_t)b * T_ * SP_;
    const int li0 = tid, li1 = tid + 544;
    float4 r0 = make_float4(0.f, 0.f, 0.f, 0.f), r1 = r0;
    {
        const float4* src = (const float4*)Pb;
        if (li0 < 1040) r0 = src[li0];
        if (li1 < 1040) r1 = src[li1];
        float4* dst = (float4*)&buf[0][0][0];
        if (li0 < 1040) dst[li0] = r0;
        if (li1 < 1040) dst[li1] = r1;
    }
    __syncthreads();

    float Cacc = 0.f;
    for (int c = 0; c < NC_; c++) {
        if (c + 1 < NC_) {
            const float4* src = (const float4*)(Pb + (size_t)(c + 1) * CH_ * SP_);
            if (li0 < 1040) r0 = src[li0];
            if (li1 < 1040) r1 = src[li1];
        }
        const int cur = c & 1;
#pragma unroll
        for (int tr = 0; tr < CH_; tr++) {
            const int tg = c * CH_ + tr;
            float val = 0.f;
            if (active) {
                float P = buf[cur][tr][s];
                if (tg == 0) {
                    val = (s == 0 || (s == 1 && tl > 0)) ? P : 0.f;
                } else {
                    float a  = sa[2 + s];
                    float a1 = sa[1 + s];
                    float a2 = skip ? sa[s] : 0.f;
                    val = (a + a1 + a2) * P;
                }
            }
            __syncthreads();
            if (active && (tg == 0 || tg < inlen)) sa[2 + s] = val;
            __syncthreads();
        }
        if (c + 1 < NC_) {
            float4* dst = (float4*)&buf[cur ^ 1][0][0];
            if (li0 < 1040) dst[li0] = r0;
            if (li1 < 1040) dst[li1] = r1;
        }
        float mv = active ? sa[2 + s] : 0.f;
        mv = warpReduceMaxF(mv);
        if ((tid & 31) == 0) warpred[tid >> 5] = mv;
        __syncthreads();
        if (tid == 0) {
            float r = warpred[0];
#pragma unroll
            for (int i = 1; i < 17; i++) r = fmaxf(r, warpred[i]);
            if (r > 0.f) { s_inv = 1.0f / r; Cacc += __logf(r); }
            else s_inv = 1.0f;
        }
        __syncthreads();
        if (active) sa[2 + s] *= s_inv;
        __syncthreads();
    }

    if (tid == 0) {
        int il2 = 2 * tl;
        float al = sa[2 + il2];
        float ap = (tl > 0) ? sa[2 + il2 - 1] : 0.f;
        float per = -(__logf(al + ap) + Cacc + Msum[b]);
        float tld = (float)(tl > 0 ? tl : 1);
        atomicAdd(loss_slot, per / (tld * (float)B_));
    }
}

__global__ void finalize_kernel(float* out, int loss_off)
{
    float v = out[loss_off];
    if (!isfinite(v)) out[loss_off] = 0.f;
}

// -------------------- launch ------------------------------------------------
extern "C" void kernel_launch(void* const* d_in, const int* in_sizes, int n_in,
                              void* d_out, int out_size)
{
    const float* rep  = (const float*)d_in[0];
    const int*   encm = (const int*)d_in[1];
    const int*   tgt  = (const int*)d_in[2];
    const int*   tgtm = (const int*)d_in[3];
    const float* Wexp = (const float*)d_in[4];
    const float* bexp = (const float*)d_in[5];
    const float* W1   = (const float*)d_in[6];
    const float* b1   = (const float*)d_in[7];
    const float* W2   = (const float*)d_in[8];
    const float* b2   = (const float*)d_in[9];
    float* out = (float*)d_out;

    __half *p_repf, *p_Wet, *p_W1t, *p_W2t, *p_st, *p_H;
    float *p_logits, *p_Pext, *p_mt, *p_Msum;
    int *p_tlen, *p_olen;
    cudaGetSymbolAddress((void**)&p_repf, g_repf);
    cudaGetSymbolAddress((void**)&p_Wet, g_Wexpt);
    cudaGetSymbolAddress((void**)&p_W1t, g_W1t);
    cudaGetSymbolAddress((void**)&p_W2t, g_W2t);
    cudaGetSymbolAddress((void**)&p_st, g_st);
    cudaGetSymbolAddress((void**)&p_H, g_H);
    cudaGetSymbolAddress((void**)&p_logits, g_logits);
    cudaGetSymbolAddress((void**)&p_Pext, g_Pext);
    cudaGetSymbolAddress((void**)&p_mt, g_mt);
    cudaGetSymbolAddress((void**)&p_Msum, g_Msum);
    cudaGetSymbolAddress((void**)&p_tlen, g_tlen);
    cudaGetSymbolAddress((void**)&p_olen, g_olen);

    const int SMEM_GEMM = 3 * 32768;  // 96 KB -> 2 CTAs/SM
    cudaFuncSetAttribute(gemm_f16<false, false>, cudaFuncAttributeMaxDynamicSharedMemorySize, SMEM_GEMM);
    cudaFuncSetAttribute(gemm_f16<true,  false>, cudaFuncAttributeMaxDynamicSharedMemorySize, SMEM_GEMM);
    cudaFuncSetAttribute(gemm_f16<false, true >, cudaFuncAttributeMaxDynamicSharedMemorySize, SMEM_GEMM);

    // convert inputs to fp16
    conv_rep_kernel<<<8192, 256>>>(rep, p_repf);
    wtrans_kernel<<<dim3(2048 / 32, 512 / 32), 256>>>(Wexp, p_Wet, 512, 2048);
    wtrans_kernel<<<dim3(1024 / 32, 512 / 32), 256>>>(W1, p_W1t, 512, 1024);
    wtrans_kernel<<<dim3(512 / 32, 1024 / 32), 256>>>(W2, p_W2t, 1024, 512);

    // GEMM1: states[16384,2048] = rep @ Wexp + bexp  (fp16 out)
    gemm_f16<false, false><<<dim3(16, 128), 256, SMEM_GEMM>>>(
        p_repf, p_Wet, bexp, p_st, nullptr, 16384, 2048, 512);
    // GEMM2: H[65536,1024] = relu(states @ W1 + b1)  (fp16 out)
    gemm_f16<true, false><<<dim3(8, 512), 256, SMEM_GEMM>>>(
        p_st, p_W1t, b1, p_H, nullptr, 65536, 1024, 512);
    // GEMM3: logits[65536,512] = H @ W2 + b2  (fp32 out)
    gemm_f16<false, true><<<dim3(4, 512), 256, SMEM_GEMM>>>(
        p_H, p_W2t, b2, nullptr, p_logits, 65536, 512, 1024);

    const int loss_off = out_size - 1;
    const int len_off  = out_size - 1 - B_;
    lengths_kernel<<<B_, 256>>>(encm, tgtm, out, len_off, loss_off, p_tlen, p_olen);
    softmax_gather_kernel<<<B_ * T_, 256>>>(p_logits, tgt, out, p_Pext, p_mt);
    msum_kernel<<<B_, 256>>>(p_mt, p_olen, p_Msum);
    ctc_dp_kernel<<<B_, 544>>>(p_Pext, p_Msum, tgt, p_tlen, p_olen, out + loss_off);
    finalize_kernel<<<1, 1>>>(out, loss_off);
}

// round 9
// speedup vs baseline: 4.8061x; 1.1383x over previous
#include <cuda_runtime.h>
#include <cuda_fp16.h>
#include <math.h>
#include <stdint.h>

// Problem constants
#define B_   32
#define SSRC 512
#define D_   512
#define STR_ 4
#define T_   2048
#define V_   512
#define L_   256
#define S_   513
#define SP_  520
#define CH_  8
#define NC_  (T_/CH_)

// -------------------- scratch (device globals) ----------------------------
__device__ __half g_repf[(size_t)16384 * 512];
__device__ __half g_Wexpf[(size_t)512 * 2048];   // Wexp fp16 (no transpose)
__device__ __half g_W1t[(size_t)1024 * 512];     // W1^T fp16
__device__ __half g_W2t[(size_t)512 * 1024];     // W2^T fp16
__device__ __half g_Bc[(size_t)4096 * 512];      // merged weight [nq, e]
__device__ float  g_bc[4096];                     // merged bias
__device__ float  g_zb[512];                      // zero bias (zero-initialized)
__device__ __half g_H[(size_t)65536 * 1024];     // hidden fp16 (== [16384,4096])
__device__ float g_logits[(size_t)65536 * 512];
__device__ __align__(16) __half g_Pexth[(size_t)B_ * T_ * SP_];
__device__ float g_mt[B_ * T_];
__device__ float g_Msum[B_];
__device__ int   g_tlen[B_];
__device__ int   g_olen[B_];

// -------------------- helpers ---------------------------------------------
__device__ __forceinline__ float warpReduceMaxF(float v) {
#pragma unroll
    for (int o = 16; o > 0; o >>= 1) v = fmaxf(v, __shfl_xor_sync(0xffffffffu, v, o));
    return v;
}
__device__ __forceinline__ float warpReduceSumF(float v) {
#pragma unroll
    for (int o = 16; o > 0; o >>= 1) v += __shfl_xor_sync(0xffffffffu, v, o);
    return v;
}
__device__ __forceinline__ int warpReduceSumI(int v) {
#pragma unroll
    for (int o = 16; o > 0; o >>= 1) v += __shfl_xor_sync(0xffffffffu, v, o);
    return v;
}
__device__ __forceinline__ uint32_t smem_u32(const void* p) {
    uint32_t a;
    asm("{ .reg .u64 t; cvta.to.shared.u64 t, %1; cvt.u32.u64 %0, t; }" : "=r"(a) : "l"(p));
    return a;
}
__device__ __forceinline__ uint32_t swz128(uint32_t x) { return x ^ ((x >> 3) & 0x70u); }

__device__ __forceinline__ void cpa16(uint32_t dst, const void* src) {
    asm volatile("cp.async.cg.shared.global [%0], [%1], 16;" :: "r"(dst), "l"(src));
}
#define CP_COMMIT() asm volatile("cp.async.commit_group;" ::: "memory")
#define CP_WAIT0()  asm volatile("cp.async.wait_group 0;" ::: "memory")
#define CP_WAIT1()  asm volatile("cp.async.wait_group 1;" ::: "memory")

__device__ __forceinline__ void ldsm4(uint32_t* r, uint32_t a) {
    asm volatile("ldmatrix.sync.aligned.m8n8.x4.shared.b16 {%0,%1,%2,%3}, [%4];"
        : "=r"(r[0]), "=r"(r[1]), "=r"(r[2]), "=r"(r[3]) : "r"(a));
}
__device__ __forceinline__ void mma16816(float* c, const uint32_t* a, uint32_t b0, uint32_t b1) {
    asm volatile("mma.sync.aligned.m16n8k16.row.col.f32.f16.f16.f32 "
        "{%0,%1,%2,%3}, {%4,%5,%6,%7}, {%8,%9}, {%0,%1,%2,%3};"
        : "+f"(c[0]), "+f"(c[1]), "+f"(c[2]), "+f"(c[3])
        : "r"(a[0]), "r"(a[1]), "r"(a[2]), "r"(a[3]), "r"(b0), "r"(b1));
}

// -------------------- input conversion kernels -----------------------------
__global__ __launch_bounds__(256) void conv_f16_kernel(
    const float* __restrict__ x, __half* __restrict__ h)
{
    int i = blockIdx.x * 256 + threadIdx.x;
    float4 v = ((const float4*)x)[i];
    __half2 h01 = __floats2half2_rn(v.x, v.y);
    __half2 h23 = __floats2half2_rn(v.z, v.w);
    ((__half2*)h)[2 * i]     = h01;
    ((__half2*)h)[2 * i + 1] = h23;
}

// W [K,N] row-major -> T [N,K] fp16
__global__ __launch_bounds__(256) void wtrans_kernel(
    const float* __restrict__ W, __half* __restrict__ Th, int K, int N)
{
    __shared__ float tile[32][33];
    const int bx = blockIdx.x, by = blockIdx.y;
    const int tx = threadIdx.x & 31, ty = threadIdx.x >> 5;
#pragma unroll
    for (int i = 0; i < 4; i++)
        tile[ty + i * 8][tx] = W[(size_t)(by * 32 + ty + i * 8) * N + bx * 32 + tx];
    __syncthreads();
#pragma unroll
    for (int i = 0; i < 4; i++) {
        float v = tile[tx][ty + i * 8];
        size_t o = (size_t)(bx * 32 + ty + i * 8) * K + by * 32 + tx;
        Th[o] = __float2half_rn(v);
    }
}

// bc[r*1024+n] = b1[n] + sum_k bexp[r*512+k] * W1[k,n]
__global__ __launch_bounds__(1024) void bias_fold_kernel(
    const float* __restrict__ bexp, const float* __restrict__ W1,
    const float* __restrict__ b1, float* __restrict__ bc)
{
    const int r = blockIdx.x;
    const int n = threadIdx.x;
    float acc = b1[n];
    for (int k = 0; k < 512; k++)
        acc += bexp[r * 512 + k] * W1[(size_t)k * 1024 + n];
    bc[r * 1024 + n] = acc;
}

// -------------------- fp16 mma.sync GEMM -----------------------------------
// C[M,N] = A[M,K] @ B[N,K]^T + bias (ldc = N).  Block 128x128, K-chunk 64,
// 3-stage cp.async pipeline, 256 threads, target occupancy 2.
template <bool RELU, bool OUTF32>
__global__ __launch_bounds__(256, 2) void gemm_f16(
    const __half* __restrict__ A, int lda,
    const __half* __restrict__ Bw, int ldb,
    const float* __restrict__ bias,
    __half* __restrict__ Ch, float* __restrict__ Cf,
    int M, int N, int K)
{
    constexpr uint32_t OFF_B = 16384;
    constexpr uint32_t STAGE = 32768;
    extern __shared__ __align__(16) char dsm[];   // 3 stages x 32 KB
    const uint32_t sbase = smem_u32(dsm);
    const int tid = threadIdx.x;
    const int lane = tid & 31, w = tid >> 5;
    const int m0 = blockIdx.y * 128;
    const int n0 = blockIdx.x * 128;
    const int wm0 = (w >> 1) * 32;
    const int wn0 = (w & 1) * 64;
    const int nch = K >> 6;

    const int lrow = tid >> 3;        // 0..31
    const int lcg  = tid & 7;         // 16B group within 128B row
    const char* pA = (const char*)A;
    const char* pB = (const char*)Bw;

#define ISSUE(k0, sb_)                                                         \
    {                                                                          \
        uint32_t sb = (sb_);                                                   \
        _Pragma("unroll")                                                      \
        for (int j = 0; j < 4; j++) {                                          \
            int r = lrow + j * 32;                                             \
            uint32_t so = swz128((uint32_t)(r * 128 + lcg * 16));              \
            size_t goA = ((size_t)(m0 + r) * lda + (k0) + lcg * 8) * 2;        \
            size_t goB = ((size_t)(n0 + r) * ldb + (k0) + lcg * 8) * 2;        \
            cpa16(sb + so, pA + goA);                                          \
            cpa16(sb + OFF_B + so, pB + goB);                                  \
        }                                                                      \
    }

    float acc[2][8][4];
#pragma unroll
    for (int mt = 0; mt < 2; mt++)
#pragma unroll
        for (int nt = 0; nt < 8; nt++)
#pragma unroll
            for (int q = 0; q < 4; q++) acc[mt][nt][q] = 0.f;

    const uint32_t stg[3] = {sbase, sbase + STAGE, sbase + 2 * STAGE};

    ISSUE(0, stg[0]); CP_COMMIT();
    ISSUE(64, stg[1]); CP_COMMIT();

    const int rl = ((lane >> 3) & 1) * 8 + (lane & 7);
    const int kb = (lane >> 4) * 8;

    int cs = 0;      // compute stage
    int is2 = 2;     // stage for chunk c+2
#pragma unroll 1
    for (int c = 0; c < nch; c++) {
        if (c == nch - 1) { CP_WAIT0(); } else { CP_WAIT1(); }
        __syncthreads();
        if (c + 2 < nch) {
            ISSUE((c + 2) << 6, stg[is2]); CP_COMMIT();
            if (++is2 == 3) is2 = 0;
        }

        const uint32_t a_b = stg[cs];
        const uint32_t b_b = a_b + OFF_B;
        if (++cs == 3) cs = 0;
#pragma unroll
        for (int ks = 0; ks < 4; ks++) {
            const uint32_t kof = (uint32_t)((ks * 16 + kb) * 2);
            uint32_t aH[2][4];
#pragma unroll
            for (int mt = 0; mt < 2; mt++) {
                uint32_t off = swz128((uint32_t)((wm0 + mt * 16 + rl) * 128) + kof);
                ldsm4(aH[mt], a_b + off);
            }
            uint32_t bH[4][4];
#pragma unroll
            for (int ng = 0; ng < 4; ng++) {
                uint32_t off = swz128((uint32_t)((wn0 + ng * 16 + rl) * 128) + kof);
                ldsm4(bH[ng], b_b + off);
            }
#pragma unroll
            for (int mt = 0; mt < 2; mt++)
#pragma unroll
                for (int nt = 0; nt < 8; nt++) {
                    const int ng = nt >> 1, sl = nt & 1;
                    mma16816(acc[mt][nt], aH[mt], bH[ng][sl], bH[ng][sl + 2]);
                }
        }
    }

    // epilogue (fp16 or f32 out)
#pragma unroll
    for (int mt = 0; mt < 2; mt++) {
#pragma unroll
        for (int nt = 0; nt < 8; nt++) {
            const int row = m0 + wm0 + mt * 16 + (lane >> 2);
            const int col = n0 + wn0 + nt * 8 + (lane & 3) * 2;
            float bv0 = __ldg(bias + col);
            float bv1 = __ldg(bias + col + 1);
            float v00 = acc[mt][nt][0] + bv0;
            float v01 = acc[mt][nt][1] + bv1;
            float v10 = acc[mt][nt][2] + bv0;
            float v11 = acc[mt][nt][3] + bv1;
            if (RELU) {
                v00 = fmaxf(v00, 0.f); v01 = fmaxf(v01, 0.f);
                v10 = fmaxf(v10, 0.f); v11 = fmaxf(v11, 0.f);
            }
            size_t g0 = (size_t)row * N + col;
            size_t g1 = (size_t)(row + 8) * N + col;
            if (OUTF32) {
                *(float2*)(Cf + g0) = make_float2(v00, v01);
                *(float2*)(Cf + g1) = make_float2(v10, v11);
            } else {
                *(__half2*)(Ch + g0) = __floats2half2_rn(v00, v01);
                *(__half2*)(Ch + g1) = __floats2half2_rn(v10, v11);
            }
        }
    }
#undef ISSUE
}

// -------------------- fused log-softmax + label gather ---------------------
__global__ __launch_bounds__(256) void softmax_gather_kernel(
    const float* __restrict__ logits, const int* __restrict__ targets,
    float* __restrict__ lp_out, __half* __restrict__ Pext, float* __restrict__ mt)
{
    const int row = blockIdx.x;
    const int b   = row >> 11;
    const int tid = threadIdx.x;
    const int lane = tid & 31, wid = tid >> 5;
    const float* x = logits + (size_t)row * V_;

    __shared__ float sh_e[V_];
    __shared__ float sh_g[S_];
    __shared__ float red[8];

    float v0 = x[tid];
    float v1 = x[tid + 256];
    float m = fmaxf(v0, v1);
    m = warpReduceMaxF(m);
    if (lane == 0) red[wid] = m;
    __syncthreads();
    float mm = red[0];
#pragma unroll
    for (int i = 1; i < 8; i++) mm = fmaxf(mm, red[i]);
    __syncthreads();

    float e0 = __expf(v0 - mm), e1 = __expf(v1 - mm);
    sh_e[tid] = e0;
    sh_e[tid + 256] = e1;
    float sm = warpReduceSumF(e0 + e1);
    if (lane == 0) red[wid] = sm;
    __syncthreads();
    float ssum = red[0];
#pragma unroll
    for (int i = 1; i < 8; i++) ssum += red[i];

    float lse = __logf(ssum);
    lp_out[(size_t)row * V_ + tid] = v0 - mm - lse;
    lp_out[(size_t)row * V_ + tid + 256] = v1 - mm - lse;

    float pm = 0.f;
    for (int s = tid; s < S_; s += 256) {
        int lab = (s & 1) ? targets[b * L_ + (s >> 1)] : 1;
        float p = sh_e[lab];
        sh_g[s] = p;
        pm = fmaxf(pm, p);
    }
    pm = warpReduceMaxF(pm);
    __syncthreads();
    if (lane == 0) red[wid] = pm;
    __syncthreads();
    float pmax = red[0];
#pragma unroll
    for (int i = 1; i < 8; i++) pmax = fmaxf(pmax, red[i]);
    float inv = 1.0f / pmax;
    for (int s = tid; s < S_; s += 256)
        Pext[(size_t)row * SP_ + s] = __float2half_rn(sh_g[s] * inv);
    if (tid == 0) mt[row] = __logf(pmax) - lse;
}

// -------------------- lengths ----------------------------------------------
__global__ __launch_bounds__(256) void lengths_kernel(
    const int* __restrict__ encm, const int* __restrict__ tgtm,
    float* __restrict__ out, int len_off, int loss_off,
    int* __restrict__ tlen, int* __restrict__ olen)
{
    const int b = blockIdx.x, tid = threadIdx.x;
    const int lane = tid & 31, wid = tid >> 5;
    int c1 = 0;
    for (int i = tid; i < SSRC; i += 256) c1 += (encm[b * SSRC + i] != 0);
    int c2 = 0;
    for (int i = tid; i < L_; i += 256) c2 += (tgtm[b * L_ + i] != 0);
    c1 = warpReduceSumI(c1);
    c2 = warpReduceSumI(c2);
    __shared__ int redi[16];
    if (lane == 0) { redi[wid] = c1; redi[8 + wid] = c2; }
    __syncthreads();
    if (tid == 0) {
        int a = 0, t = 0;
#pragma unroll
        for (int i = 0; i < 8; i++) { a += redi[i]; t += redi[8 + i]; }
        olen[b] = STR_ * a;
        tlen[b] = t;
        out[len_off + b] = (float)(STR_ * a);
        if (b == 0) out[loss_off] = 0.f;
    }
}

// -------------------- msum -------------------------------------------------
__global__ __launch_bounds__(256) void msum_kernel(
    const float* __restrict__ mt, const int* __restrict__ olen,
    float* __restrict__ Msum)
{
    const int b = blockIdx.x, tid = threadIdx.x;
    int il = olen[b]; if (il > T_) il = T_;
    float sacc = 0.f;
    for (int t = tid; t < il; t += 256) sacc += mt[b * T_ + t];
    sacc = warpReduceSumF(sacc);
    __shared__ float red[8];
    if ((tid & 31) == 0) red[tid >> 5] = sacc;
    __syncthreads();
    if (tid == 0) {
        float r = 0.f;
#pragma unroll
        for (int i = 0; i < 8; i++) r += red[i];
        Msum[b] = r;
    }
}

// -------------------- CTC forward DP (prob domain, fp16 P, ping-pong) ------
__global__ __launch_bounds__(544) void ctc_dp_kernel(
    const __half* __restrict__ Pext, const float* __restrict__ Msum,
    const int* __restrict__ targets, const int* __restrict__ tlen,
    const int* __restrict__ olen, float* __restrict__ loss_slot)
{
    const int b = blockIdx.x;
    const int tid = threadIdx.x;
    __shared__ float sA[546], sB[546];
    __shared__ __align__(16) __half bufh[2][CH_][SP_];
    __shared__ float warpred[17];
    __shared__ float s_inv;

    const int s = tid;
    const bool active = (s < S_);
    bool skip = false;
    if (active && (s & 1)) {
        int l = s >> 1;
        int tc = targets[b * L_ + l];
        bool ok = (tc != 1);
        if (l > 0) ok = ok && (tc != targets[b * L_ + l - 1]);
        skip = ok;
    }
    const int inlen = olen[b];
    const int tl = tlen[b];

    sA[tid] = 0.f; sB[tid] = 0.f;
    if (tid < 2) { sA[544 + tid] = 0.f; sB[544 + tid] = 0.f; }

    const __half* Pb = Pext + (size_t)b * T_ * SP_;
    // chunk = 8 rows x 520 halves = 520 uint4
    uint4 r0 = make_uint4(0, 0, 0, 0);
    const bool ldact = (tid < 520);
    if (ldact) r0 = ((const uint4*)Pb)[tid];
    if (ldact) ((uint4*)&bufh[0][0][0])[tid] = r0;
    __syncthreads();

    float* cur = sA;
    float* nxt = sB;
    float Cacc = 0.f;
    for (int c = 0; c < NC_; c++) {
        if (c + 1 < NC_ && ldact)
            r0 = ((const uint4*)(Pb + (size_t)(c + 1) * CH_ * SP_))[tid];
        const int cb = c & 1;
#pragma unroll
        for (int tr = 0; tr < CH_; tr++) {
            const int tg = c * CH_ + tr;
            if (active) {
                float P = __half2float(bufh[cb][tr][s]);
                float val;
                if (tg == 0) {
                    val = (s == 0 || (s == 1 && tl > 0)) ? P : 0.f;
                } else {
                    float a  = cur[2 + s];
                    float a1 = cur[1 + s];
                    float a2 = skip ? cur[s] : 0.f;
                    val = (a + a1 + a2) * P;
                    if (tg >= inlen) val = a;   // freeze past input length
                }
                nxt[2 + s] = val;
            }
            __syncthreads();
            { float* tmp = cur; cur = nxt; nxt = tmp; }
        }
        if (c + 1 < NC_ && ldact)
            ((uint4*)&bufh[cb ^ 1][0][0])[tid] = r0;
        // renorm every chunk; barriers also protect the bufh write above
        float mv = active ? cur[2 + s] : 0.f;
        mv = warpReduceMaxF(mv);
        if ((tid & 31) == 0) warpred[tid >> 5] = mv;
        __syncthreads();
        if (tid == 0) {
            float r = warpred[0];
#pragma unroll
            for (int i = 1; i < 17; i++) r = fmaxf(r, warpred[i]);
            if (r > 0.f) { s_inv = 1.0f / r; Cacc += __logf(r); }
            else s_inv = 1.0f;
        }
        __syncthreads();
        if (active) cur[2 + s] *= s_inv;
        __syncthreads();
    }

    if (tid == 0) {
        int il2 = 2 * tl;
        float al = cur[2 + il2];
        float ap = (tl > 0) ? cur[1 + il2] : 0.f;
        float per = -(__logf(al + ap) + Cacc + Msum[b]);
        float tld = (float)(tl > 0 ? tl : 1);
        atomicAdd(loss_slot, per / (tld * (float)B_));
    }
}

__global__ void finalize_kernel(float* out, int loss_off)
{
    float v = out[loss_off];
    if (!isfinite(v)) out[loss_off] = 0.f;
}

// -------------------- launch ------------------------------------------------
extern "C" void kernel_launch(void* const* d_in, const int* in_sizes, int n_in,
                              void* d_out, int out_size)
{
    const float* rep  = (const float*)d_in[0];
    const int*   encm = (const int*)d_in[1];
    const int*   tgt  = (const int*)d_in[2];
    const int*   tgtm = (const int*)d_in[3];
    const float* Wexp = (const float*)d_in[4];
    const float* bexp = (const float*)d_in[5];
    const float* W1   = (const float*)d_in[6];
    const float* b1   = (const float*)d_in[7];
    const float* W2   = (const float*)d_in[8];
    const float* b2   = (const float*)d_in[9];
    float* out = (float*)d_out;

    __half *p_repf, *p_Wexpf, *p_W1t, *p_W2t, *p_Bc, *p_H;
    __half *p_Pexth;
    float *p_bc, *p_zb, *p_logits, *p_mt, *p_Msum;
    int *p_tlen, *p_olen;
    cudaGetSymbolAddress((void**)&p_repf, g_repf);
    cudaGetSymbolAddress((void**)&p_Wexpf, g_Wexpf);
    cudaGetSymbolAddress((void**)&p_W1t, g_W1t);
    cudaGetSymbolAddress((void**)&p_W2t, g_W2t);
    cudaGetSymbolAddress((void**)&p_Bc, g_Bc);
    cudaGetSymbolAddress((void**)&p_bc, g_bc);
    cudaGetSymbolAddress((void**)&p_zb, g_zb);
    cudaGetSymbolAddress((void**)&p_H, g_H);
    cudaGetSymbolAddress((void**)&p_logits, g_logits);
    cudaGetSymbolAddress((void**)&p_Pexth, g_Pexth);
    cudaGetSymbolAddress((void**)&p_mt, g_mt);
    cudaGetSymbolAddress((void**)&p_Msum, g_Msum);
    cudaGetSymbolAddress((void**)&p_tlen, g_tlen);
    cudaGetSymbolAddress((void**)&p_olen, g_olen);

    const int SMEM_GEMM = 3 * 32768;  // 96 KB -> 2 CTAs/SM
    cudaFuncSetAttribute(gemm_f16<false, false>, cudaFuncAttributeMaxDynamicSharedMemorySize, SMEM_GEMM);
    cudaFuncSetAttribute(gemm_f16<true,  false>, cudaFuncAttributeMaxDynamicSharedMemorySize, SMEM_GEMM);
    cudaFuncSetAttribute(gemm_f16<false, true >, cudaFuncAttributeMaxDynamicSharedMemorySize, SMEM_GEMM);

    // conversions
    conv_f16_kernel<<<8192, 256>>>(rep, p_repf);           // 16384x512
    conv_f16_kernel<<<1024, 256>>>(Wexp, p_Wexpf);         // 512x2048 (no transpose)
    wtrans_kernel<<<dim3(1024 / 32, 512 / 32), 256>>>(W1, p_W1t, 512, 1024);
    wtrans_kernel<<<dim3(512 / 32, 1024 / 32), 256>>>(W2, p_W2t, 1024, 512);
    bias_fold_kernel<<<4, 1024>>>(bexp, W1, b1, p_bc);

    // precompute merged weight: Bc[r*1024+n, e] = sum_d W1[d,n]*Wexp[e, r*512+d]
    // = gemm(A=W1t[1024,512], B=Wexpf+r*512 (ldb 2048), M=1024, N=512, K=512)
    for (int r = 0; r < 4; r++) {
        gemm_f16<false, false><<<dim3(4, 8), 256, SMEM_GEMM>>>(
            p_W1t, 512, p_Wexpf + r * 512, 2048, p_zb,
            p_Bc + (size_t)r * 1024 * 512, nullptr, 1024, 512, 512);
    }

    // merged GEMM: H[16384,4096] = relu(rep @ Bc^T + bc)  (fp16 out)
    gemm_f16<true, false><<<dim3(32, 128), 256, SMEM_GEMM>>>(
        p_repf, 512, p_Bc, 512, p_bc, p_H, nullptr, 16384, 4096, 512);
    // GEMM3: logits[65536,512] = H @ W2 + b2  (fp32 out); H viewed as [65536,1024]
    gemm_f16<false, true><<<dim3(4, 512), 256, SMEM_GEMM>>>(
        p_H, 1024, p_W2t, 1024, b2, nullptr, p_logits, 65536, 512, 1024);

    const int loss_off = out_size - 1;
    const int len_off  = out_size - 1 - B_;
    lengths_kernel<<<B_, 256>>>(encm, tgtm, out, len_off, loss_off, p_tlen, p_olen);
    softmax_gather_kernel<<<B_ * T_, 256>>>(p_logits, tgt, out, p_Pexth, p_mt);
    msum_kernel<<<B_, 256>>>(p_mt, p_olen, p_Msum);
    ctc_dp_kernel<<<B_, 544>>>(p_Pexth, p_Msum, tgt, p_tlen, p_olen, out + loss_off);
    finalize_kernel<<<1, 1>>>(out, loss_off);
}

// round 10
// speedup vs baseline: 4.9647x; 1.0330x over previous
#include <cuda_runtime.h>
#include <cuda_fp16.h>
#include <math.h>
#include <stdint.h>

// Problem constants
#define B_   32
#define SSRC 512
#define D_   512
#define STR_ 4
#define T_   2048
#define V_   512
#define L_   256
#define S_   513
#define SP_  520
#define CH_  8
#define NC_  (T_/CH_)

// -------------------- scratch (device globals) ----------------------------
__device__ __half g_repf[(size_t)16384 * 512];
__device__ __half g_Wexpf[(size_t)512 * 2048];   // Wexp fp16 (no transpose)
__device__ __half g_W1t[(size_t)1024 * 512];     // W1^T fp16
__device__ __half g_W2t[(size_t)512 * 1024];     // W2^T fp16
__device__ __half g_Bc[(size_t)4096 * 512];      // merged weight [nq, e]
__device__ float  g_bc[4096];                     // merged bias
__device__ float  g_zb[512];                      // zero bias (zero-initialized)
__device__ __half g_H[(size_t)65536 * 1024];     // hidden fp16 (== [16384,4096])
__device__ float g_logits[(size_t)65536 * 512];
__device__ __align__(16) __half g_Pexth[(size_t)B_ * T_ * SP_];
__device__ float g_Msum[B_];
__device__ int   g_tlen[B_];
__device__ int   g_olen[B_];

// -------------------- helpers ---------------------------------------------
__device__ __forceinline__ float warpReduceMaxF(float v) {
#pragma unroll
    for (int o = 16; o > 0; o >>= 1) v = fmaxf(v, __shfl_xor_sync(0xffffffffu, v, o));
    return v;
}
__device__ __forceinline__ float warpReduceSumF(float v) {
#pragma unroll
    for (int o = 16; o > 0; o >>= 1) v += __shfl_xor_sync(0xffffffffu, v, o);
    return v;
}
__device__ __forceinline__ int warpReduceSumI(int v) {
#pragma unroll
    for (int o = 16; o > 0; o >>= 1) v += __shfl_xor_sync(0xffffffffu, v, o);
    return v;
}
__device__ __forceinline__ uint32_t smem_u32(const void* p) {
    uint32_t a;
    asm("{ .reg .u64 t; cvta.to.shared.u64 t, %1; cvt.u32.u64 %0, t; }" : "=r"(a) : "l"(p));
    return a;
}
__device__ __forceinline__ uint32_t swz128(uint32_t x) { return x ^ ((x >> 3) & 0x70u); }

__device__ __forceinline__ void cpa16(uint32_t dst, const void* src) {
    asm volatile("cp.async.cg.shared.global [%0], [%1], 16;" :: "r"(dst), "l"(src));
}
#define CP_COMMIT() asm volatile("cp.async.commit_group;" ::: "memory")
#define CP_WAIT0()  asm volatile("cp.async.wait_group 0;" ::: "memory")
#define CP_WAIT1()  asm volatile("cp.async.wait_group 1;" ::: "memory")

__device__ __forceinline__ void ldsm4(uint32_t* r, uint32_t a) {
    asm volatile("ldmatrix.sync.aligned.m8n8.x4.shared.b16 {%0,%1,%2,%3}, [%4];"
        : "=r"(r[0]), "=r"(r[1]), "=r"(r[2]), "=r"(r[3]) : "r"(a));
}
__device__ __forceinline__ void mma16816(float* c, const uint32_t* a, uint32_t b0, uint32_t b1) {
    asm volatile("mma.sync.aligned.m16n8k16.row.col.f32.f16.f16.f32 "
        "{%0,%1,%2,%3}, {%4,%5,%6,%7}, {%8,%9}, {%0,%1,%2,%3};"
        : "+f"(c[0]), "+f"(c[1]), "+f"(c[2]), "+f"(c[3])
        : "r"(a[0]), "r"(a[1]), "r"(a[2]), "r"(a[3]), "r"(b0), "r"(b1));
}

// -------------------- input conversion kernels -----------------------------
__global__ __launch_bounds__(256) void conv_f16_kernel(
    const float* __restrict__ x, __half* __restrict__ h)
{
    int i = blockIdx.x * 256 + threadIdx.x;
    float4 v = ((const float4*)x)[i];
    __half2 h01 = __floats2half2_rn(v.x, v.y);
    __half2 h23 = __floats2half2_rn(v.z, v.w);
    ((__half2*)h)[2 * i]     = h01;
    ((__half2*)h)[2 * i + 1] = h23;
}

// W [K,N] row-major -> T [N,K] fp16
__global__ __launch_bounds__(256) void wtrans_kernel(
    const float* __restrict__ W, __half* __restrict__ Th, int K, int N)
{
    __shared__ float tile[32][33];
    const int bx = blockIdx.x, by = blockIdx.y;
    const int tx = threadIdx.x & 31, ty = threadIdx.x >> 5;
#pragma unroll
    for (int i = 0; i < 4; i++)
        tile[ty + i * 8][tx] = W[(size_t)(by * 32 + ty + i * 8) * N + bx * 32 + tx];
    __syncthreads();
#pragma unroll
    for (int i = 0; i < 4; i++) {
        float v = tile[tx][ty + i * 8];
        size_t o = (size_t)(bx * 32 + ty + i * 8) * K + by * 32 + tx;
        Th[o] = __float2half_rn(v);
    }
}

// bc[r*1024+n] = b1[n] + sum_k bexp[r*512+k] * W1[k,n]
__global__ __launch_bounds__(1024) void bias_fold_kernel(
    const float* __restrict__ bexp, const float* __restrict__ W1,
    const float* __restrict__ b1, float* __restrict__ bc)
{
    const int r = blockIdx.x;
    const int n = threadIdx.x;
    float acc = b1[n];
    for (int k = 0; k < 512; k++)
        acc += bexp[r * 512 + k] * W1[(size_t)k * 1024 + n];
    bc[r * 1024 + n] = acc;
}

// -------------------- fp16 mma.sync GEMM -----------------------------------
// C[M,N] = A[M,K] @ B[N,K]^T + bias (ldc = N).  Block 128x128, K-chunk 64,
// 3-stage cp.async pipeline, 256 threads, occupancy 2.
// blockIdx.z batching: B += z*bzs elements, C += z*czs elements.
template <bool RELU, bool OUTF32>
__global__ __launch_bounds__(256, 2) void gemm_f16(
    const __half* __restrict__ A, int lda,
    const __half* __restrict__ Bw, int ldb,
    const float* __restrict__ bias,
    __half* __restrict__ Ch, float* __restrict__ Cf,
    int M, int N, int K, int bzs, int czs)
{
    constexpr uint32_t OFF_B = 16384;
    constexpr uint32_t STAGE = 32768;
    extern __shared__ __align__(16) char dsm[];   // 3 stages x 32 KB
    const uint32_t sbase = smem_u32(dsm);
    const int tid = threadIdx.x;
    const int lane = tid & 31, w = tid >> 5;
    const int z = blockIdx.z;
    const int m0 = blockIdx.y * 128;
    const int n0 = blockIdx.x * 128;
    const int wm0 = (w >> 1) * 32;
    const int wn0 = (w & 1) * 64;
    const int nch = K >> 6;

    const int lrow = tid >> 3;        // 0..31
    const int lcg  = tid & 7;         // 16B group within 128B row
    const char* pA = (const char*)A;
    const char* pB = (const char*)Bw + (size_t)z * bzs * 2;

#define ISSUE(k0, sb_)                                                         \
    {                                                                          \
        uint32_t sb = (sb_);                                                   \
        _Pragma("unroll")                                                      \
        for (int j = 0; j < 4; j++) {                                          \
            int r = lrow + j * 32;                                             \
            uint32_t so = swz128((uint32_t)(r * 128 + lcg * 16));              \
            size_t goA = ((size_t)(m0 + r) * lda + (k0) + lcg * 8) * 2;        \
            size_t goB = ((size_t)(n0 + r) * ldb + (k0) + lcg * 8) * 2;        \
            cpa16(sb + so, pA + goA);                                          \
            cpa16(sb + OFF_B + so, pB + goB);                                  \
        }                                                                      \
    }

    float acc[2][8][4];
#pragma unroll
    for (int mt = 0; mt < 2; mt++)
#pragma unroll
        for (int nt = 0; nt < 8; nt++)
#pragma unroll
            for (int q = 0; q < 4; q++) acc[mt][nt][q] = 0.f;

    const uint32_t stg[3] = {sbase, sbase + STAGE, sbase + 2 * STAGE};

    ISSUE(0, stg[0]); CP_COMMIT();
    ISSUE(64, stg[1]); CP_COMMIT();

    const int rl = ((lane >> 3) & 1) * 8 + (lane & 7);
    const int kb = (lane >> 4) * 8;

    int cs = 0;      // compute stage
    int is2 = 2;     // stage for chunk c+2
#pragma unroll 1
    for (int c = 0; c < nch; c++) {
        if (c == nch - 1) { CP_WAIT0(); } else { CP_WAIT1(); }
        __syncthreads();
        if (c + 2 < nch) {
            ISSUE((c + 2) << 6, stg[is2]); CP_COMMIT();
            if (++is2 == 3) is2 = 0;
        }

        const uint32_t a_b = stg[cs];
        const uint32_t b_b = a_b + OFF_B;
        if (++cs == 3) cs = 0;
#pragma unroll
        for (int ks = 0; ks < 4; ks++) {
            const uint32_t kof = (uint32_t)((ks * 16 + kb) * 2);
            uint32_t aH[2][4];
#pragma unroll
            for (int mt = 0; mt < 2; mt++) {
                uint32_t off = swz128((uint32_t)((wm0 + mt * 16 + rl) * 128) + kof);
                ldsm4(aH[mt], a_b + off);
            }
            uint32_t bH[4][4];
#pragma unroll
            for (int ng = 0; ng < 4; ng++) {
                uint32_t off = swz128((uint32_t)((wn0 + ng * 16 + rl) * 128) + kof);
                ldsm4(bH[ng], b_b + off);
            }
#pragma unroll
            for (int mt = 0; mt < 2; mt++)
#pragma unroll
                for (int nt = 0; nt < 8; nt++) {
                    const int ng = nt >> 1, sl = nt & 1;
                    mma16816(acc[mt][nt], aH[mt], bH[ng][sl], bH[ng][sl + 2]);
                }
        }
    }

    // epilogue (fp16 or f32 out)
#pragma unroll
    for (int mt = 0; mt < 2; mt++) {
#pragma unroll
        for (int nt = 0; nt < 8; nt++) {
            const int row = m0 + wm0 + mt * 16 + (lane >> 2);
            const int col = n0 + wn0 + nt * 8 + (lane & 3) * 2;
            float bv0 = __ldg(bias + col);
            float bv1 = __ldg(bias + col + 1);
            float v00 = acc[mt][nt][0] + bv0;
            float v01 = acc[mt][nt][1] + bv1;
            float v10 = acc[mt][nt][2] + bv0;
            float v11 = acc[mt][nt][3] + bv1;
            if (RELU) {
                v00 = fmaxf(v00, 0.f); v01 = fmaxf(v01, 0.f);
                v10 = fmaxf(v10, 0.f); v11 = fmaxf(v11, 0.f);
            }
            size_t g0 = (size_t)row * N + col + (size_t)z * czs;
            size_t g1 = (size_t)(row + 8) * N + col + (size_t)z * czs;
            if (OUTF32) {
                *(float2*)(Cf + g0) = make_float2(v00, v01);
                *(float2*)(Cf + g1) = make_float2(v10, v11);
            } else {
                *(__half2*)(Ch + g0) = __floats2half2_rn(v00, v01);
                *(__half2*)(Ch + g1) = __floats2half2_rn(v10, v11);
            }
        }
    }
#undef ISSUE
}

// -------------------- fused log-softmax + gather + msum --------------------
__global__ __launch_bounds__(256) void softmax_gather_kernel(
    const float* __restrict__ logits, const int* __restrict__ targets,
    float* __restrict__ lp_out, __half* __restrict__ Pext,
    const int* __restrict__ olen, float* __restrict__ Msum)
{
    const int row = blockIdx.x;
    const int b   = row >> 11;
    const int t   = row & (T_ - 1);
    const int tid = threadIdx.x;
    const int lane = tid & 31, wid = tid >> 5;
    const float* x = logits + (size_t)row * V_;

    __shared__ float sh_e[V_];
    __shared__ float sh_g[S_];
    __shared__ float red[8];

    float v0 = x[tid];
    float v1 = x[tid + 256];
    float m = fmaxf(v0, v1);
    m = warpReduceMaxF(m);
    if (lane == 0) red[wid] = m;
    __syncthreads();
    float mm = red[0];
#pragma unroll
    for (int i = 1; i < 8; i++) mm = fmaxf(mm, red[i]);
    __syncthreads();

    float e0 = __expf(v0 - mm), e1 = __expf(v1 - mm);
    sh_e[tid] = e0;
    sh_e[tid + 256] = e1;
    float sm = warpReduceSumF(e0 + e1);
    if (lane == 0) red[wid] = sm;
    __syncthreads();
    float ssum = red[0];
#pragma unroll
    for (int i = 1; i < 8; i++) ssum += red[i];

    float lse = __logf(ssum);
    lp_out[(size_t)row * V_ + tid] = v0 - mm - lse;
    lp_out[(size_t)row * V_ + tid + 256] = v1 - mm - lse;

    float pm = 0.f;
    for (int s = tid; s < S_; s += 256) {
        int lab = (s & 1) ? targets[b * L_ + (s >> 1)] : 1;
        float p = sh_e[lab];
        sh_g[s] = p;
        pm = fmaxf(pm, p);
    }
    pm = warpReduceMaxF(pm);
    __syncthreads();
    if (lane == 0) red[wid] = pm;
    __syncthreads();
    float pmax = red[0];
#pragma unroll
    for (int i = 1; i < 8; i++) pmax = fmaxf(pmax, red[i]);
    float inv = 1.0f / pmax;
    for (int s = tid; s < S_; s += 256)
        Pext[(size_t)row * SP_ + s] = __float2half_rn(sh_g[s] * inv);
    if (tid == 0 && t < olen[b])
        atomicAdd(&Msum[b], __logf(pmax) - lse);
}

// -------------------- lengths (also zeroes Msum) ----------------------------
__global__ __launch_bounds__(256) void lengths_kernel(
    const int* __restrict__ encm, const int* __restrict__ tgtm,
    float* __restrict__ out, int len_off, int loss_off,
    int* __restrict__ tlen, int* __restrict__ olen, float* __restrict__ Msum)
{
    const int b = blockIdx.x, tid = threadIdx.x;
    const int lane = tid & 31, wid = tid >> 5;
    int c1 = 0;
    for (int i = tid; i < SSRC; i += 256) c1 += (encm[b * SSRC + i] != 0);
    int c2 = 0;
    for (int i = tid; i < L_; i += 256) c2 += (tgtm[b * L_ + i] != 0);
    c1 = warpReduceSumI(c1);
    c2 = warpReduceSumI(c2);
    __shared__ int redi[16];
    if (lane == 0) { redi[wid] = c1; redi[8 + wid] = c2; }
    __syncthreads();
    if (tid == 0) {
        int a = 0, t = 0;
#pragma unroll
        for (int i = 0; i < 8; i++) { a += redi[i]; t += redi[8 + i]; }
        olen[b] = STR_ * a;
        tlen[b] = t;
        Msum[b] = 0.f;
        out[len_off + b] = (float)(STR_ * a);
        if (b == 0) out[loss_off] = 0.f;
    }
}

// -------------------- CTC forward DP (2 steps per barrier) ------------------
// 544 threads, 1 state/thread. Each pair (t+1,t+2): thread computes step t+1
// redundantly for states {s, s-1, s-2}, then step t+2 for s. 1024 barriers.
// P chunks: window of 2 chunks (16 rows) resident; buf[(chunk)&1].
__global__ __launch_bounds__(544) void ctc_dp_kernel(
    const __half* __restrict__ Pext, const float* __restrict__ Msum,
    const int* __restrict__ targets, const int* __restrict__ tlen,
    const int* __restrict__ olen, float* __restrict__ loss_slot)
{
    const int b = blockIdx.x;
    const int tid = threadIdx.x;
    __shared__ float sA[548], sB[548];     // 4 pads + 544 states
    __shared__ __align__(16) __half bufh[2][CH_][SP_];
    __shared__ float warpred[17];
    __shared__ float s_inv;

    const int s = tid;
    const bool active = (s < S_);
    const int inlen = olen[b];
    const int tl = tlen[b];

    // skip flags for states s, s-1, s-2
    bool k0 = false, k1 = false, k2 = false;
    {
        const int* tg = targets + b * L_;
#define SKIPAT(x, out)                                                        \
        if ((x) >= 1 && ((x) & 1)) {                                          \
            int l = (x) >> 1;                                                 \
            int tc = tg[l];                                                   \
            out = (tc != 1) && (l == 0 || tc != tg[l - 1]);                   \
        }
        if (active) { SKIPAT(s, k0); SKIPAT(s - 1, k1); SKIPAT(s - 2, k2); }
#undef SKIPAT
    }

    sA[tid] = 0.f; sB[tid] = 0.f;
    if (tid < 4) { sA[544 + tid] = 0.f; sB[544 + tid] = 0.f; }

    const __half* Pb = Pext + (size_t)b * T_ * SP_;
    // preload chunks 0 and 1 (2 x 520 uint4, contiguous in bufh)
    {
        const int li0 = tid, li1 = tid + 544;
        uint4 r0, r1;
        if (li0 < 1040) r0 = ((const uint4*)Pb)[li0];
        if (li1 < 1040) r1 = ((const uint4*)Pb)[li1];
        if (li0 < 1040) ((uint4*)&bufh[0][0][0])[li0] = r0;
        if (li1 < 1040) ((uint4*)&bufh[0][0][0])[li1] = r1;
    }
    __syncthreads();

    // t = 0 init
    float* cur = sA;
    float* nxt = sB;
    if (active) {
        float P0 = __half2float(bufh[0][0][s]);
        cur[4 + s] = (s == 0 || (s == 1 && tl > 0)) ? P0 : 0.f;
    }
    __syncthreads();

    const int sm1 = (s >= 1) ? s - 1 : 0;
    const int sm2 = (s >= 2) ? s - 2 : 0;

    float Cacc = 0.f;
    uint4 rp;
    const bool ldact = (tid < 520);
#pragma unroll 1
    for (int c = 0; c < NC_; c++) {
        if (c + 2 < NC_ && ldact)
            rp = ((const uint4*)(Pb + (size_t)(c + 2) * CH_ * SP_))[tid];
        const int cb = c & 1;
#pragma unroll
        for (int q = 0; q < 4; q++) {
            const int t1 = 8 * c + 2 * q + 1;
            const int t2 = t1 + 1;
            if (active) {
                float a0 = cur[4 + s];
                float a1 = cur[3 + s];
                float a2 = cur[2 + s];
                float a3 = cur[1 + s];
                float a4 = cur[s];
                const __half* row1 = &bufh[cb][2 * q + 1][0];
                float P1s  = __half2float(row1[s]);
                float P1m1 = __half2float(row1[sm1]);
                float P1m2 = __half2float(row1[sm2]);
                float P2s  = (q < 3) ? __half2float(bufh[cb][2 * q + 2][s])
                                     : __half2float(bufh[cb ^ 1][0][s]);
                bool fr1 = (t1 >= inlen);
                bool fr2 = (t2 >= inlen);
                float v1s  = fr1 ? a0 : (a0 + a1 + (k0 ? a2 : 0.f)) * P1s;
                float v1m1 = fr1 ? a1 : (a1 + a2 + (k1 ? a3 : 0.f)) * P1m1;
                float v1m2 = fr1 ? a2 : (a2 + a3 + (k2 ? a4 : 0.f)) * P1m2;
                float v2s  = fr2 ? v1s : (v1s + v1m1 + (k0 ? v1m2 : 0.f)) * P2s;
                nxt[4 + s] = v2s;
            }
            __syncthreads();
            { float* tmp = cur; cur = nxt; nxt = tmp; }
        }
        // overwrite consumed chunk c with chunk c+2
        if (c + 2 < NC_ && ldact)
            ((uint4*)&bufh[cb][0][0])[tid] = rp;
        // renorm every 8 steps; its barriers also protect the bufh write
        float mv = active ? cur[4 + s] : 0.f;
        mv = warpReduceMaxF(mv);
        if ((tid & 31) == 0) warpred[tid >> 5] = mv;
        __syncthreads();
        if (tid == 0) {
            float r = warpred[0];
#pragma unroll
            for (int i = 1; i < 17; i++) r = fmaxf(r, warpred[i]);
            if (r > 0.f) { s_inv = 1.0f / r; Cacc += __logf(r); }
            else s_inv = 1.0f;
        }
        __syncthreads();
        if (active) cur[4 + s] *= s_inv;
        __syncthreads();
    }

    if (tid == 0) {
        int il2 = 2 * tl;
        float al = cur[4 + il2];
        float ap = (tl > 0) ? cur[3 + il2] : 0.f;
        float per = -(__logf(al + ap) + Cacc + Msum[b]);
        float tld = (float)(tl > 0 ? tl : 1);
        atomicAdd(loss_slot, per / (tld * (float)B_));
    }
}

__global__ void finalize_kernel(float* out, int loss_off)
{
    float v = out[loss_off];
    if (!isfinite(v)) out[loss_off] = 0.f;
}

// -------------------- launch ------------------------------------------------
extern "C" void kernel_launch(void* const* d_in, const int* in_sizes, int n_in,
                              void* d_out, int out_size)
{
    const float* rep  = (const float*)d_in[0];
    const int*   encm = (const int*)d_in[1];
    const int*   tgt  = (const int*)d_in[2];
    const int*   tgtm = (const int*)d_in[3];
    const float* Wexp = (const float*)d_in[4];
    const float* bexp = (const float*)d_in[5];
    const float* W1   = (const float*)d_in[6];
    const float* b1   = (const float*)d_in[7];
    const float* W2   = (const float*)d_in[8];
    const float* b2   = (const float*)d_in[9];
    float* out = (float*)d_out;

    __half *p_repf, *p_Wexpf, *p_W1t, *p_W2t, *p_Bc, *p_H, *p_Pexth;
    float *p_bc, *p_zb, *p_logits, *p_Msum;
    int *p_tlen, *p_olen;
    cudaGetSymbolAddress((void**)&p_repf, g_repf);
    cudaGetSymbolAddress((void**)&p_Wexpf, g_Wexpf);
    cudaGetSymbolAddress((void**)&p_W1t, g_W1t);
    cudaGetSymbolAddress((void**)&p_W2t, g_W2t);
    cudaGetSymbolAddress((void**)&p_Bc, g_Bc);
    cudaGetSymbolAddress((void**)&p_bc, g_bc);
    cudaGetSymbolAddress((void**)&p_zb, g_zb);
    cudaGetSymbolAddress((void**)&p_H, g_H);
    cudaGetSymbolAddress((void**)&p_logits, g_logits);
    cudaGetSymbolAddress((void**)&p_Pexth, g_Pexth);
    cudaGetSymbolAddress((void**)&p_Msum, g_Msum);
    cudaGetSymbolAddress((void**)&p_tlen, g_tlen);
    cudaGetSymbolAddress((void**)&p_olen, g_olen);

    const int SMEM_GEMM = 3 * 32768;  // 96 KB -> 2 CTAs/SM
    cudaFuncSetAttribute(gemm_f16<false, false>, cudaFuncAttributeMaxDynamicSharedMemorySize, SMEM_GEMM);
    cudaFuncSetAttribute(gemm_f16<true,  false>, cudaFuncAttributeMaxDynamicSharedMemorySize, SMEM_GEMM);
    cudaFuncSetAttribute(gemm_f16<false, true >, cudaFuncAttributeMaxDynamicSharedMemorySize, SMEM_GEMM);

    // conversions
    conv_f16_kernel<<<8192, 256>>>(rep, p_repf);           // 16384x512
    conv_f16_kernel<<<1024, 256>>>(Wexp, p_Wexpf);         // 512x2048
    wtrans_kernel<<<dim3(1024 / 32, 512 / 32), 256>>>(W1, p_W1t, 512, 1024);
    wtrans_kernel<<<dim3(512 / 32, 1024 / 32), 256>>>(W2, p_W2t, 1024, 512);
    bias_fold_kernel<<<4, 1024>>>(bexp, W1, b1, p_bc);

    // merged weight Bc: single launch, blockIdx.z = r
    // Bc[r*1024+n, e] = sum_d W1[d,n]*Wexp[e? -> verified layout in R9]
    gemm_f16<false, false><<<dim3(4, 8, 4), 256, SMEM_GEMM>>>(
        p_W1t, 512, p_Wexpf, 2048, p_zb,
        p_Bc, nullptr, 1024, 512, 512, /*bzs=*/512, /*czs=*/1024 * 512);

    // merged GEMM: H[16384,4096] = relu(rep @ Bc^T + bc)  (fp16 out)
    gemm_f16<true, false><<<dim3(32, 128, 1), 256, SMEM_GEMM>>>(
        p_repf, 512, p_Bc, 512, p_bc, p_H, nullptr, 16384, 4096, 512, 0, 0);
    // GEMM3: logits[65536,512] = H @ W2 + b2  (fp32 out); H viewed as [65536,1024]
    gemm_f16<false, true><<<dim3(4, 512, 1), 256, SMEM_GEMM>>>(
        p_H, 1024, p_W2t, 1024, b2, nullptr, p_logits, 65536, 512, 1024, 0, 0);

    const int loss_off = out_size - 1;
    const int len_off  = out_size - 1 - B_;
    lengths_kernel<<<B_, 256>>>(encm, tgtm, out, len_off, loss_off, p_tlen, p_olen, p_Msum);
    softmax_gather_kernel<<<B_ * T_, 256>>>(p_logits, tgt, out, p_Pexth, p_olen, p_Msum);
    ctc_dp_kernel<<<B_, 544>>>(p_Pexth, p_Msum, tgt, p_tlen, p_olen, out + loss_off);
    finalize_kernel<<<1, 1>>>(out, loss_off);
}

// round 11
// speedup vs baseline: 5.2665x; 1.0608x over previous
#include <cuda_runtime.h>
#include <cuda_fp16.h>
#include <math.h>
#include <stdint.h>

// Problem constants
#define B_   32
#define SSRC 512
#define D_   512
#define STR_ 4
#define T_   2048
#define V_   512
#define L_   256
#define S_   513
#define SP_  520
#define CH_  8
#define NC_  (T_/CH_)

// -------------------- scratch (device globals) ----------------------------
__device__ __half g_repf[(size_t)16384 * 512];
__device__ __half g_Wexpf[(size_t)512 * 2048];   // Wexp fp16 (no transpose)
__device__ __half g_W1t[(size_t)1024 * 512];     // W1^T fp16
__device__ __half g_W2t[(size_t)512 * 1024];     // W2^T fp16
__device__ __half g_Bc[(size_t)4096 * 512];      // merged weight [nq, e]
__device__ float  g_bc[4096];                     // merged bias
__device__ float  g_zb[512];                      // zero bias (zero-initialized)
__device__ __half g_H[(size_t)65536 * 1024];     // hidden fp16 (== [16384,4096])
__device__ __half g_logitsh[(size_t)65536 * 512];
__device__ __align__(16) __half g_Pexth[(size_t)B_ * T_ * SP_];
__device__ float g_Msum[B_];
__device__ int   g_tlen[B_];
__device__ int   g_olen[B_];

// -------------------- helpers ---------------------------------------------
__device__ __forceinline__ float warpReduceMaxF(float v) {
#pragma unroll
    for (int o = 16; o > 0; o >>= 1) v = fmaxf(v, __shfl_xor_sync(0xffffffffu, v, o));
    return v;
}
__device__ __forceinline__ float warpReduceSumF(float v) {
#pragma unroll
    for (int o = 16; o > 0; o >>= 1) v += __shfl_xor_sync(0xffffffffu, v, o);
    return v;
}
__device__ __forceinline__ int warpReduceSumI(int v) {
#pragma unroll
    for (int o = 16; o > 0; o >>= 1) v += __shfl_xor_sync(0xffffffffu, v, o);
    return v;
}
__device__ __forceinline__ uint32_t smem_u32(const void* p) {
    uint32_t a;
    asm("{ .reg .u64 t; cvta.to.shared.u64 t, %1; cvt.u32.u64 %0, t; }" : "=r"(a) : "l"(p));
    return a;
}
__device__ __forceinline__ uint32_t swz128(uint32_t x) { return x ^ ((x >> 3) & 0x70u); }

__device__ __forceinline__ void cpa16(uint32_t dst, const void* src) {
    asm volatile("cp.async.cg.shared.global [%0], [%1], 16;" :: "r"(dst), "l"(src));
}
#define CP_COMMIT() asm volatile("cp.async.commit_group;" ::: "memory")
#define CP_WAIT0()  asm volatile("cp.async.wait_group 0;" ::: "memory")
#define CP_WAIT1()  asm volatile("cp.async.wait_group 1;" ::: "memory")

__device__ __forceinline__ void ldsm4(uint32_t* r, uint32_t a) {
    asm volatile("ldmatrix.sync.aligned.m8n8.x4.shared.b16 {%0,%1,%2,%3}, [%4];"
        : "=r"(r[0]), "=r"(r[1]), "=r"(r[2]), "=r"(r[3]) : "r"(a));
}
__device__ __forceinline__ void mma16816(float* c, const uint32_t* a, uint32_t b0, uint32_t b1) {
    asm volatile("mma.sync.aligned.m16n8k16.row.col.f32.f16.f16.f32 "
        "{%0,%1,%2,%3}, {%4,%5,%6,%7}, {%8,%9}, {%0,%1,%2,%3};"
        : "+f"(c[0]), "+f"(c[1]), "+f"(c[2]), "+f"(c[3])
        : "r"(a[0]), "r"(a[1]), "r"(a[2]), "r"(a[3]), "r"(b0), "r"(b1));
}

// -------------------- input conversion kernels -----------------------------
__global__ __launch_bounds__(256) void conv_f16_kernel(
    const float* __restrict__ x, __half* __restrict__ h)
{
    int i = blockIdx.x * 256 + threadIdx.x;
    float4 v = ((const float4*)x)[i];
    __half2 h01 = __floats2half2_rn(v.x, v.y);
    __half2 h23 = __floats2half2_rn(v.z, v.w);
    ((__half2*)h)[2 * i]     = h01;
    ((__half2*)h)[2 * i + 1] = h23;
}

// W [K,N] row-major -> T [N,K] fp16
__global__ __launch_bounds__(256) void wtrans_kernel(
    const float* __restrict__ W, __half* __restrict__ Th, int K, int N)
{
    __shared__ float tile[32][33];
    const int bx = blockIdx.x, by = blockIdx.y;
    const int tx = threadIdx.x & 31, ty = threadIdx.x >> 5;
#pragma unroll
    for (int i = 0; i < 4; i++)
        tile[ty + i * 8][tx] = W[(size_t)(by * 32 + ty + i * 8) * N + bx * 32 + tx];
    __syncthreads();
#pragma unroll
    for (int i = 0; i < 4; i++) {
        float v = tile[tx][ty + i * 8];
        size_t o = (size_t)(bx * 32 + ty + i * 8) * K + by * 32 + tx;
        Th[o] = __float2half_rn(v);
    }
}

// bc[r*1024+n] = b1[n] + sum_k bexp[r*512+k] * W1[k,n]
__global__ __launch_bounds__(1024) void bias_fold_kernel(
    const float* __restrict__ bexp, const float* __restrict__ W1,
    const float* __restrict__ b1, float* __restrict__ bc)
{
    const int r = blockIdx.x;
    const int n = threadIdx.x;
    float acc = b1[n];
    for (int k = 0; k < 512; k++)
        acc += bexp[r * 512 + k] * W1[(size_t)k * 1024 + n];
    bc[r * 1024 + n] = acc;
}

// -------------------- fp16 mma.sync GEMM -----------------------------------
// C[M,N] = A[M,K] @ B[N,K]^T + bias (ldc = N).  Block 128x128, K-chunk 64,
// 3-stage cp.async pipeline, 256 threads, occupancy 2. fp16 output.
// blockIdx.z batching: B += z*bzs elements, C += z*czs elements.
template <bool RELU>
__global__ __launch_bounds__(256, 2) void gemm_f16(
    const __half* __restrict__ A, int lda,
    const __half* __restrict__ Bw, int ldb,
    const float* __restrict__ bias,
    __half* __restrict__ Ch,
    int M, int N, int K, int bzs, int czs)
{
    constexpr uint32_t OFF_B = 16384;
    constexpr uint32_t STAGE = 32768;
    extern __shared__ __align__(16) char dsm[];   // 3 stages x 32 KB
    const uint32_t sbase = smem_u32(dsm);
    const int tid = threadIdx.x;
    const int lane = tid & 31, w = tid >> 5;
    const int z = blockIdx.z;
    const int m0 = blockIdx.y * 128;
    const int n0 = blockIdx.x * 128;
    const int wm0 = (w >> 1) * 32;
    const int wn0 = (w & 1) * 64;
    const int nch = K >> 6;

    const int lrow = tid >> 3;        // 0..31
    const int lcg  = tid & 7;         // 16B group within 128B row
    const char* pA = (const char*)A;
    const char* pB = (const char*)Bw + (size_t)z * bzs * 2;

#define ISSUE(k0, sb_)                                                         \
    {                                                                          \
        uint32_t sb = (sb_);                                                   \
        _Pragma("unroll")                                                      \
        for (int j = 0; j < 4; j++) {                                          \
            int r = lrow + j * 32;                                             \
            uint32_t so = swz128((uint32_t)(r * 128 + lcg * 16));              \
            size_t goA = ((size_t)(m0 + r) * lda + (k0) + lcg * 8) * 2;        \
            size_t goB = ((size_t)(n0 + r) * ldb + (k0) + lcg * 8) * 2;        \
            cpa16(sb + so, pA + goA);                                          \
            cpa16(sb + OFF_B + so, pB + goB);                                  \
        }                                                                      \
    }

    float acc[2][8][4];
#pragma unroll
    for (int mt = 0; mt < 2; mt++)
#pragma unroll
        for (int nt = 0; nt < 8; nt++)
#pragma unroll
            for (int q = 0; q < 4; q++) acc[mt][nt][q] = 0.f;

    const uint32_t stg[3] = {sbase, sbase + STAGE, sbase + 2 * STAGE};

    ISSUE(0, stg[0]); CP_COMMIT();
    ISSUE(64, stg[1]); CP_COMMIT();

    const int rl = ((lane >> 3) & 1) * 8 + (lane & 7);
    const int kb = (lane >> 4) * 8;

    int cs = 0;      // compute stage
    int is2 = 2;     // stage for chunk c+2
#pragma unroll 1
    for (int c = 0; c < nch; c++) {
        if (c == nch - 1) { CP_WAIT0(); } else { CP_WAIT1(); }
        __syncthreads();
        if (c + 2 < nch) {
            ISSUE((c + 2) << 6, stg[is2]); CP_COMMIT();
            if (++is2 == 3) is2 = 0;
        }

        const uint32_t a_b = stg[cs];
        const uint32_t b_b = a_b + OFF_B;
        if (++cs == 3) cs = 0;
#pragma unroll
        for (int ks = 0; ks < 4; ks++) {
            const uint32_t kof = (uint32_t)((ks * 16 + kb) * 2);
            uint32_t aH[2][4];
#pragma unroll
            for (int mt = 0; mt < 2; mt++) {
                uint32_t off = swz128((uint32_t)((wm0 + mt * 16 + rl) * 128) + kof);
                ldsm4(aH[mt], a_b + off);
            }
            uint32_t bH[4][4];
#pragma unroll
            for (int ng = 0; ng < 4; ng++) {
                uint32_t off = swz128((uint32_t)((wn0 + ng * 16 + rl) * 128) + kof);
                ldsm4(bH[ng], b_b + off);
            }
#pragma unroll
            for (int mt = 0; mt < 2; mt++)
#pragma unroll
                for (int nt = 0; nt < 8; nt++) {
                    const int ng = nt >> 1, sl = nt & 1;
                    mma16816(acc[mt][nt], aH[mt], bH[ng][sl], bH[ng][sl + 2]);
                }
        }
    }

    // epilogue (fp16 out)
#pragma unroll
    for (int mt = 0; mt < 2; mt++) {
#pragma unroll
        for (int nt = 0; nt < 8; nt++) {
            const int row = m0 + wm0 + mt * 16 + (lane >> 2);
            const int col = n0 + wn0 + nt * 8 + (lane & 3) * 2;
            float bv0 = __ldg(bias + col);
            float bv1 = __ldg(bias + col + 1);
            float v00 = acc[mt][nt][0] + bv0;
            float v01 = acc[mt][nt][1] + bv1;
            float v10 = acc[mt][nt][2] + bv0;
            float v11 = acc[mt][nt][3] + bv1;
            if (RELU) {
                v00 = fmaxf(v00, 0.f); v01 = fmaxf(v01, 0.f);
                v10 = fmaxf(v10, 0.f); v11 = fmaxf(v11, 0.f);
            }
            size_t g0 = (size_t)row * N + col + (size_t)z * czs;
            size_t g1 = (size_t)(row + 8) * N + col + (size_t)z * czs;
            *(__half2*)(Ch + g0) = __floats2half2_rn(v00, v01);
            *(__half2*)(Ch + g1) = __floats2half2_rn(v10, v11);
        }
    }
#undef ISSUE
}

// -------------------- fused log-softmax + gather + msum --------------------
// fp16 logits in; fp32 logprobs out (required dtype); fp16 Pext out.
__global__ __launch_bounds__(256) void softmax_gather_kernel(
    const __half* __restrict__ logits, const int* __restrict__ targets,
    float* __restrict__ lp_out, __half* __restrict__ Pext,
    const int* __restrict__ olen, float* __restrict__ Msum)
{
    const int row = blockIdx.x;
    const int b   = row >> 11;
    const int t   = row & (T_ - 1);
    const int tid = threadIdx.x;
    const int lane = tid & 31, wid = tid >> 5;
    const __half2* x = (const __half2*)(logits + (size_t)row * V_);

    __shared__ float sh_e[V_];
    __shared__ float sh_g[S_];
    __shared__ float red[8];

    __half2 hv = x[tid];
    float v0 = __low2float(hv);
    float v1 = __high2float(hv);
    float m = fmaxf(v0, v1);
    m = warpReduceMaxF(m);
    if (lane == 0) red[wid] = m;
    __syncthreads();
    float mm = red[0];
#pragma unroll
    for (int i = 1; i < 8; i++) mm = fmaxf(mm, red[i]);
    __syncthreads();

    float e0 = __expf(v0 - mm), e1 = __expf(v1 - mm);
    sh_e[2 * tid] = e0;
    sh_e[2 * tid + 1] = e1;
    float sm = warpReduceSumF(e0 + e1);
    if (lane == 0) red[wid] = sm;
    __syncthreads();
    float ssum = red[0];
#pragma unroll
    for (int i = 1; i < 8; i++) ssum += red[i];

    float lse = __logf(ssum);
    ((float2*)(lp_out + (size_t)row * V_))[tid] =
        make_float2(v0 - mm - lse, v1 - mm - lse);

    float pm = 0.f;
    for (int s = tid; s < S_; s += 256) {
        int lab = (s & 1) ? targets[b * L_ + (s >> 1)] : 1;
        float p = sh_e[lab];
        sh_g[s] = p;
        pm = fmaxf(pm, p);
    }
    pm = warpReduceMaxF(pm);
    __syncthreads();
    if (lane == 0) red[wid] = pm;
    __syncthreads();
    float pmax = red[0];
#pragma unroll
    for (int i = 1; i < 8; i++) pmax = fmaxf(pmax, red[i]);
    float inv = 1.0f / pmax;
    for (int s = tid; s < S_; s += 256)
        Pext[(size_t)row * SP_ + s] = __float2half_rn(sh_g[s] * inv);
    if (tid == 0 && t < olen[b])
        atomicAdd(&Msum[b], __logf(pmax) - lse);
}

// -------------------- lengths (also zeroes Msum) ----------------------------
__global__ __launch_bounds__(256) void lengths_kernel(
    const int* __restrict__ encm, const int* __restrict__ tgtm,
    float* __restrict__ out, int len_off, int loss_off,
    int* __restrict__ tlen, int* __restrict__ olen, float* __restrict__ Msum)
{
    const int b = blockIdx.x, tid = threadIdx.x;
    const int lane = tid & 31, wid = tid >> 5;
    int c1 = 0;
    for (int i = tid; i < SSRC; i += 256) c1 += (encm[b * SSRC + i] != 0);
    int c2 = 0;
    for (int i = tid; i < L_; i += 256) c2 += (tgtm[b * L_ + i] != 0);
    c1 = warpReduceSumI(c1);
    c2 = warpReduceSumI(c2);
    __shared__ int redi[16];
    if (lane == 0) { redi[wid] = c1; redi[8 + wid] = c2; }
    __syncthreads();
    if (tid == 0) {
        int a = 0, t = 0;
#pragma unroll
        for (int i = 0; i < 8; i++) { a += redi[i]; t += redi[8 + i]; }
        olen[b] = STR_ * a;
        tlen[b] = t;
        Msum[b] = 0.f;
        out[len_off + b] = (float)(STR_ * a);
        if (b == 0) out[loss_off] = 0.f;
    }
}

// -------------------- CTC forward DP (2 steps per barrier) ------------------
// 544 threads, 1 state/thread. Each pair (t+1,t+2): thread computes step t+1
// redundantly for states {s, s-1, s-2}, then step t+2 for s. 1024 barriers.
// Renorm every 2 chunks (16 steps). P chunks: 2-chunk resident window.
__global__ __launch_bounds__(544) void ctc_dp_kernel(
    const __half* __restrict__ Pext, const float* __restrict__ Msum,
    const int* __restrict__ targets, const int* __restrict__ tlen,
    const int* __restrict__ olen, float* __restrict__ loss_slot)
{
    const int b = blockIdx.x;
    const int tid = threadIdx.x;
    __shared__ float sA[548], sB[548];     // 4 pads + 544 states
    __shared__ __align__(16) __half bufh[2][CH_][SP_];
    __shared__ float warpred[17];
    __shared__ float s_inv;

    const int s = tid;
    const bool active = (s < S_);
    const int inlen = olen[b];
    const int tl = tlen[b];

    // skip flags for states s, s-1, s-2
    bool k0 = false, k1 = false, k2 = false;
    {
        const int* tg = targets + b * L_;
#define SKIPAT(x, out)                                                        \
        if ((x) >= 1 && ((x) & 1)) {                                          \
            int l = (x) >> 1;                                                 \
            int tc = tg[l];                                                   \
            out = (tc != 1) && (l == 0 || tc != tg[l - 1]);                   \
        }
        if (active) { SKIPAT(s, k0); SKIPAT(s - 1, k1); SKIPAT(s - 2, k2); }
#undef SKIPAT
    }

    sA[tid] = 0.f; sB[tid] = 0.f;
    if (tid < 4) { sA[544 + tid] = 0.f; sB[544 + tid] = 0.f; }

    const __half* Pb = Pext + (size_t)b * T_ * SP_;
    // preload chunks 0 and 1 (2 x 520 uint4, contiguous in bufh)
    {
        const int li0 = tid, li1 = tid + 544;
        uint4 r0, r1;
        if (li0 < 1040) r0 = ((const uint4*)Pb)[li0];
        if (li1 < 1040) r1 = ((const uint4*)Pb)[li1];
        if (li0 < 1040) ((uint4*)&bufh[0][0][0])[li0] = r0;
        if (li1 < 1040) ((uint4*)&bufh[0][0][0])[li1] = r1;
    }
    __syncthreads();

    // t = 0 init
    float* cur = sA;
    float* nxt = sB;
    if (active) {
        float P0 = __half2float(bufh[0][0][s]);
        cur[4 + s] = (s == 0 || (s == 1 && tl > 0)) ? P0 : 0.f;
    }
    __syncthreads();

    const int sm1 = (s >= 1) ? s - 1 : 0;
    const int sm2 = (s >= 2) ? s - 2 : 0;

    float Cacc = 0.f;
    uint4 rp;
    const bool ldact = (tid < 520);
#pragma unroll 1
    for (int c = 0; c < NC_; c++) {
        if (c + 2 < NC_ && ldact)
            rp = ((const uint4*)(Pb + (size_t)(c + 2) * CH_ * SP_))[tid];
        const int cb = c & 1;
#pragma unroll
        for (int q = 0; q < 4; q++) {
            const int t1 = 8 * c + 2 * q + 1;
            const int t2 = t1 + 1;
            if (active) {
                float a0 = cur[4 + s];
                float a1 = cur[3 + s];
                float a2 = cur[2 + s];
                float a3 = cur[1 + s];
                float a4 = cur[s];
                const __half* row1 = &bufh[cb][2 * q + 1][0];
                float P1s  = __half2float(row1[s]);
                float P1m1 = __half2float(row1[sm1]);
                float P1m2 = __half2float(row1[sm2]);
                float P2s  = (q < 3) ? __half2float(bufh[cb][2 * q + 2][s])
                                     : __half2float(bufh[cb ^ 1][0][s]);
                bool fr1 = (t1 >= inlen);
                bool fr2 = (t2 >= inlen);
                float v1s  = fr1 ? a0 : (a0 + a1 + (k0 ? a2 : 0.f)) * P1s;
                float v1m1 = fr1 ? a1 : (a1 + a2 + (k1 ? a3 : 0.f)) * P1m1;
                float v1m2 = fr1 ? a2 : (a2 + a3 + (k2 ? a4 : 0.f)) * P1m2;
                float v2s  = fr2 ? v1s : (v1s + v1m1 + (k0 ? v1m2 : 0.f)) * P2s;
                nxt[4 + s] = v2s;
            }
            __syncthreads();
            { float* tmp = cur; cur = nxt; nxt = tmp; }
        }
        // overwrite consumed chunk c with chunk c+2 (safe: earliest read of
        // this bank is 3 q-barriers into the next chunk)
        if (c + 2 < NC_ && ldact)
            ((uint4*)&bufh[cb][0][0])[tid] = rp;
        // renorm every 2 chunks (16 steps); barriers also publish bufh write
        if (cb == 1) {
            float mv = active ? cur[4 + s] : 0.f;
            mv = warpReduceMaxF(mv);
            if ((tid & 31) == 0) warpred[tid >> 5] = mv;
            __syncthreads();
            if (tid == 0) {
                float r = warpred[0];
#pragma unroll
                for (int i = 1; i < 17; i++) r = fmaxf(r, warpred[i]);
                if (r > 0.f) { s_inv = 1.0f / r; Cacc += __logf(r); }
                else s_inv = 1.0f;
            }
            __syncthreads();
            if (active) cur[4 + s] *= s_inv;
            __syncthreads();
        }
    }

    if (tid == 0) {
        int il2 = 2 * tl;
        float al = cur[4 + il2];
        float ap = (tl > 0) ? cur[3 + il2] : 0.f;
        float per = -(__logf(al + ap) + Cacc + Msum[b]);
        float tld = (float)(tl > 0 ? tl : 1);
        atomicAdd(loss_slot, per / (tld * (float)B_));
    }
}

__global__ void finalize_kernel(float* out, int loss_off)
{
    float v = out[loss_off];
    if (!isfinite(v)) out[loss_off] = 0.f;
}

// -------------------- launch ------------------------------------------------
extern "C" void kernel_launch(void* const* d_in, const int* in_sizes, int n_in,
                              void* d_out, int out_size)
{
    const float* rep  = (const float*)d_in[0];
    const int*   encm = (const int*)d_in[1];
    const int*   tgt  = (const int*)d_in[2];
    const int*   tgtm = (const int*)d_in[3];
    const float* Wexp = (const float*)d_in[4];
    const float* bexp = (const float*)d_in[5];
    const float* W1   = (const float*)d_in[6];
    const float* b1   = (const float*)d_in[7];
    const float* W2   = (const float*)d_in[8];
    const float* b2   = (const float*)d_in[9];
    float* out = (float*)d_out;

    __half *p_repf, *p_Wexpf, *p_W1t, *p_W2t, *p_Bc, *p_H, *p_logitsh, *p_Pexth;
    float *p_bc, *p_zb, *p_Msum;
    int *p_tlen, *p_olen;
    cudaGetSymbolAddress((void**)&p_repf, g_repf);
    cudaGetSymbolAddress((void**)&p_Wexpf, g_Wexpf);
    cudaGetSymbolAddress((void**)&p_W1t, g_W1t);
    cudaGetSymbolAddress((void**)&p_W2t, g_W2t);
    cudaGetSymbolAddress((void**)&p_Bc, g_Bc);
    cudaGetSymbolAddress((void**)&p_bc, g_bc);
    cudaGetSymbolAddress((void**)&p_zb, g_zb);
    cudaGetSymbolAddress((void**)&p_H, g_H);
    cudaGetSymbolAddress((void**)&p_logitsh, g_logitsh);
    cudaGetSymbolAddress((void**)&p_Pexth, g_Pexth);
    cudaGetSymbolAddress((void**)&p_Msum, g_Msum);
    cudaGetSymbolAddress((void**)&p_tlen, g_tlen);
    cudaGetSymbolAddress((void**)&p_olen, g_olen);

    const int SMEM_GEMM = 3 * 32768;  // 96 KB -> 2 CTAs/SM
    cudaFuncSetAttribute(gemm_f16<false>, cudaFuncAttributeMaxDynamicSharedMemorySize, SMEM_GEMM);
    cudaFuncSetAttribute(gemm_f16<true >, cudaFuncAttributeMaxDynamicSharedMemorySize, SMEM_GEMM);

    // conversions
    conv_f16_kernel<<<8192, 256>>>(rep, p_repf);           // 16384x512
    conv_f16_kernel<<<1024, 256>>>(Wexp, p_Wexpf);         // 512x2048
    wtrans_kernel<<<dim3(1024 / 32, 512 / 32), 256>>>(W1, p_W1t, 512, 1024);
    wtrans_kernel<<<dim3(512 / 32, 1024 / 32), 256>>>(W2, p_W2t, 1024, 512);
    bias_fold_kernel<<<4, 1024>>>(bexp, W1, b1, p_bc);

    // merged weight Bc: single launch, blockIdx.z = r
    gemm_f16<false><<<dim3(4, 8, 4), 256, SMEM_GEMM>>>(
        p_W1t, 512, p_Wexpf, 2048, p_zb,
        p_Bc, 1024, 512, 512, /*bzs=*/512, /*czs=*/1024 * 512);

    // merged GEMM: H[16384,4096] = relu(rep @ Bc^T + bc)  (fp16 out)
    gemm_f16<true><<<dim3(32, 128, 1), 256, SMEM_GEMM>>>(
        p_repf, 512, p_Bc, 512, p_bc, p_H, 16384, 4096, 512, 0, 0);
    // GEMM3: logits[65536,512] = H @ W2 + b2  (fp16 out); H viewed as [65536,1024]
    gemm_f16<false><<<dim3(4, 512, 1), 256, SMEM_GEMM>>>(
        p_H, 1024, p_W2t, 1024, b2, p_logitsh, 65536, 512, 1024, 0, 0);

    const int loss_off = out_size - 1;
    const int len_off  = out_size - 1 - B_;
    lengths_kernel<<<B_, 256>>>(encm, tgtm, out, len_off, loss_off, p_tlen, p_olen, p_Msum);
    softmax_gather_kernel<<<B_ * T_, 256>>>(p_logitsh, tgt, out, p_Pexth, p_olen, p_Msum);
    ctc_dp_kernel<<<B_, 544>>>(p_Pexth, p_Msum, tgt, p_tlen, p_olen, out + loss_off);
    finalize_kernel<<<1, 1>>>(out, loss_off);
}

// round 14
// speedup vs baseline: 5.4577x; 1.0363x over previous
#include <cuda_runtime.h>
#include <cuda_fp16.h>
#include <math.h>
#include <stdint.h>

// Problem constants
#define B_   32
#define SSRC 512
#define D_   512
#define STR_ 4
#define T_   2048
#define V_   512
#define L_   256
#define S_   513
#define SP_  520
#define CH_  8
#define NC_  (T_/CH_)

// -------------------- scratch (device globals) ----------------------------
__device__ __half g_repf[(size_t)16384 * 512];
__device__ __half g_Wexpf[(size_t)512 * 2048];   // Wexp fp16 (no transpose)
__device__ __half g_W1t[(size_t)1024 * 512];     // W1^T fp16
__device__ __half g_W2t[(size_t)512 * 1024];     // W2^T fp16
__device__ __half g_Bc[(size_t)4096 * 512];      // merged weight [nq, e]
__device__ float  g_bc[4096];                     // merged bias
__device__ float  g_zb[512];                      // zero bias (zero-initialized)
__device__ __half g_H[(size_t)65536 * 1024];     // hidden fp16 (== [16384,4096])
__device__ __half g_logitsh[(size_t)65536 * 512];
__device__ __align__(16) __half g_Pexth[(size_t)B_ * T_ * SP_];
__device__ float g_Msum[B_];
__device__ int   g_tlen[B_];
__device__ int   g_olen[B_];

// -------------------- helpers ---------------------------------------------
__device__ __forceinline__ float warpReduceMaxF(float v) {
#pragma unroll
    for (int o = 16; o > 0; o >>= 1) v = fmaxf(v, __shfl_xor_sync(0xffffffffu, v, o));
    return v;
}
__device__ __forceinline__ float warpReduceSumF(float v) {
#pragma unroll
    for (int o = 16; o > 0; o >>= 1) v += __shfl_xor_sync(0xffffffffu, v, o);
    return v;
}
__device__ __forceinline__ int warpReduceSumI(int v) {
#pragma unroll
    for (int o = 16; o > 0; o >>= 1) v += __shfl_xor_sync(0xffffffffu, v, o);
    return v;
}
__device__ __forceinline__ uint32_t smem_u32(const void* p) {
    uint32_t a;
    asm("{ .reg .u64 t; cvta.to.shared.u64 t, %1; cvt.u32.u64 %0, t; }" : "=r"(a) : "l"(p));
    return a;
}
__device__ __forceinline__ uint32_t swz128(uint32_t x) { return x ^ ((x >> 3) & 0x70u); }

__device__ __forceinline__ void cpa16(uint32_t dst, const void* src) {
    asm volatile("cp.async.cg.shared.global [%0], [%1], 16;" :: "r"(dst), "l"(src));
}
#define CP_COMMIT() asm volatile("cp.async.commit_group;" ::: "memory")
#define CP_WAIT0()  asm volatile("cp.async.wait_group 0;" ::: "memory")
#define CP_WAIT1()  asm volatile("cp.async.wait_group 1;" ::: "memory")

__device__ __forceinline__ void ldsm4(uint32_t* r, uint32_t a) {
    asm volatile("ldmatrix.sync.aligned.m8n8.x4.shared.b16 {%0,%1,%2,%3}, [%4];"
        : "=r"(r[0]), "=r"(r[1]), "=r"(r[2]), "=r"(r[3]) : "r"(a));
}
__device__ __forceinline__ void mma16816(float* c, const uint32_t* a, uint32_t b0, uint32_t b1) {
    asm volatile("mma.sync.aligned.m16n8k16.row.col.f32.f16.f16.f32 "
        "{%0,%1,%2,%3}, {%4,%5,%6,%7}, {%8,%9}, {%0,%1,%2,%3};"
        : "+f"(c[0]), "+f"(c[1]), "+f"(c[2]), "+f"(c[3])
        : "r"(a[0]), "r"(a[1]), "r"(a[2]), "r"(a[3]), "r"(b0), "r"(b1));
}

// -------------------- input conversion kernels -----------------------------
__global__ __launch_bounds__(256) void conv_f16_kernel(
    const float* __restrict__ x, __half* __restrict__ h)
{
    int i = blockIdx.x * 256 + threadIdx.x;
    float4 v = ((const float4*)x)[i];
    __half2 h01 = __floats2half2_rn(v.x, v.y);
    __half2 h23 = __floats2half2_rn(v.z, v.w);
    ((__half2*)h)[2 * i]     = h01;
    ((__half2*)h)[2 * i + 1] = h23;
}

// W [K,N] row-major -> T [N,K] fp16
__global__ __launch_bounds__(256) void wtrans_kernel(
    const float* __restrict__ W, __half* __restrict__ Th, int K, int N)
{
    __shared__ float tile[32][33];
    const int bx = blockIdx.x, by = blockIdx.y;
    const int tx = threadIdx.x & 31, ty = threadIdx.x >> 5;
#pragma unroll
    for (int i = 0; i < 4; i++)
        tile[ty + i * 8][tx] = W[(size_t)(by * 32 + ty + i * 8) * N + bx * 32 + tx];
    __syncthreads();
#pragma unroll
    for (int i = 0; i < 4; i++) {
        float v = tile[tx][ty + i * 8];
        size_t o = (size_t)(bx * 32 + ty + i * 8) * K + by * 32 + tx;
        Th[o] = __float2half_rn(v);
    }
}

// bc[r*1024+n] = b1[n] + sum_k bexp[r*512+k] * W1[k,n]
__global__ __launch_bounds__(1024) void bias_fold_kernel(
    const float* __restrict__ bexp, const float* __restrict__ W1,
    const float* __restrict__ b1, float* __restrict__ bc)
{
    const int r = blockIdx.x;
    const int n = threadIdx.x;
    float acc = b1[n];
    for (int k = 0; k < 512; k++)
        acc += bexp[r * 512 + k] * W1[(size_t)k * 1024 + n];
    bc[r * 1024 + n] = acc;
}

// -------------------- fp16 mma.sync GEMM -----------------------------------
// C[M,N] = A[M,K] @ B[N,K]^T + bias (ldc = N).  Block 128x128, K-chunk 64,
// 3-stage cp.async pipeline, 256 threads, occupancy 2. fp16 output.
// blockIdx.z batching: B += z*bzs elements, C += z*czs elements.
template <bool RELU>
__global__ __launch_bounds__(256, 2) void gemm_f16(
    const __half* __restrict__ A, int lda,
    const __half* __restrict__ Bw, int ldb,
    const float* __restrict__ bias,
    __half* __restrict__ Ch,
    int M, int N, int K, int bzs, int czs)
{
    constexpr uint32_t OFF_B = 16384;
    constexpr uint32_t STAGE = 32768;
    extern __shared__ __align__(16) char dsm[];   // 3 stages x 32 KB
    const uint32_t sbase = smem_u32(dsm);
    const int tid = threadIdx.x;
    const int lane = tid & 31, w = tid >> 5;
    const int z = blockIdx.z;
    const int m0 = blockIdx.y * 128;
    const int n0 = blockIdx.x * 128;
    const int wm0 = (w >> 1) * 32;
    const int wn0 = (w & 1) * 64;
    const int nch = K >> 6;

    const int lrow = tid >> 3;        // 0..31
    const int lcg  = tid & 7;         // 16B group within 128B row
    const char* pA = (const char*)A;
    const char* pB = (const char*)Bw + (size_t)z * bzs * 2;

#define ISSUE(k0, sb_)                                                         \
    {                                                                          \
        uint32_t sb = (sb_);                                                   \
        _Pragma("unroll")                                                      \
        for (int j = 0; j < 4; j++) {                                          \
            int r = lrow + j * 32;                                             \
            uint32_t so = swz128((uint32_t)(r * 128 + lcg * 16));              \
            size_t goA = ((size_t)(m0 + r) * lda + (k0) + lcg * 8) * 2;        \
            size_t goB = ((size_t)(n0 + r) * ldb + (k0) + lcg * 8) * 2;        \
            cpa16(sb + so, pA + goA);                                          \
            cpa16(sb + OFF_B + so, pB + goB);                                  \
        }                                                                      \
    }

    float acc[2][8][4];
#pragma unroll
    for (int mt = 0; mt < 2; mt++)
#pragma unroll
        for (int nt = 0; nt < 8; nt++)
#pragma unroll
            for (int q = 0; q < 4; q++) acc[mt][nt][q] = 0.f;

    const uint32_t stg[3] = {sbase, sbase + STAGE, sbase + 2 * STAGE};

    ISSUE(0, stg[0]); CP_COMMIT();
    ISSUE(64, stg[1]); CP_COMMIT();

    const int rl = ((lane >> 3) & 1) * 8 + (lane & 7);
    const int kb = (lane >> 4) * 8;

    int cs = 0;      // compute stage
    int is2 = 2;     // stage for chunk c+2
#pragma unroll 1
    for (int c = 0; c < nch; c++) {
        if (c == nch - 1) { CP_WAIT0(); } else { CP_WAIT1(); }
        __syncthreads();
        if (c + 2 < nch) {
            ISSUE((c + 2) << 6, stg[is2]); CP_COMMIT();
            if (++is2 == 3) is2 = 0;
        }

        const uint32_t a_b = stg[cs];
        const uint32_t b_b = a_b + OFF_B;
        if (++cs == 3) cs = 0;
#pragma unroll
        for (int ks = 0; ks < 4; ks++) {
            const uint32_t kof = (uint32_t)((ks * 16 + kb) * 2);
            uint32_t aH[2][4];
#pragma unroll
            for (int mt = 0; mt < 2; mt++) {
                uint32_t off = swz128((uint32_t)((wm0 + mt * 16 + rl) * 128) + kof);
                ldsm4(aH[mt], a_b + off);
            }
            uint32_t bH[4][4];
#pragma unroll
            for (int ng = 0; ng < 4; ng++) {
                uint32_t off = swz128((uint32_t)((wn0 + ng * 16 + rl) * 128) + kof);
                ldsm4(bH[ng], b_b + off);
            }
#pragma unroll
            for (int mt = 0; mt < 2; mt++)
#pragma unroll
                for (int nt = 0; nt < 8; nt++) {
                    const int ng = nt >> 1, sl = nt & 1;
                    mma16816(acc[mt][nt], aH[mt], bH[ng][sl], bH[ng][sl + 2]);
                }
        }
    }

    // epilogue (fp16 out)
#pragma unroll
    for (int mt = 0; mt < 2; mt++) {
#pragma unroll
        for (int nt = 0; nt < 8; nt++) {
            const int row = m0 + wm0 + mt * 16 + (lane >> 2);
            const int col = n0 + wn0 + nt * 8 + (lane & 3) * 2;
            float bv0 = __ldg(bias + col);
            float bv1 = __ldg(bias + col + 1);
            float v00 = acc[mt][nt][0] + bv0;
            float v01 = acc[mt][nt][1] + bv1;
            float v10 = acc[mt][nt][2] + bv0;
            float v11 = acc[mt][nt][3] + bv1;
            if (RELU) {
                v00 = fmaxf(v00, 0.f); v01 = fmaxf(v01, 0.f);
                v10 = fmaxf(v10, 0.f); v11 = fmaxf(v11, 0.f);
            }
            size_t g0 = (size_t)row * N + col + (size_t)z * czs;
            size_t g1 = (size_t)(row + 8) * N + col + (size_t)z * czs;
            *(__half2*)(Ch + g0) = __floats2half2_rn(v00, v01);
            *(__half2*)(Ch + g1) = __floats2half2_rn(v10, v11);
        }
    }
#undef ISSUE
}

// -------------------- warp-per-row log-softmax + gather + msum -------------
// 8 warps/block, one (b,t) row per warp; shuffle-only reductions.
__global__ __launch_bounds__(256) void softmax_gather_kernel(
    const __half* __restrict__ logits, const int* __restrict__ targets,
    float* __restrict__ lp_out, __half* __restrict__ Pext,
    const int* __restrict__ olen, float* __restrict__ Msum)
{
    __shared__ float sh_e[8][544];
    const int wid = threadIdx.x >> 5, lane = threadIdx.x & 31;
    const int row = blockIdx.x * 8 + wid;
    const int b = row >> 11;
    const int t = row & (T_ - 1);
    const __half2* x = (const __half2*)(logits + (size_t)row * V_);

    float v[16];
#pragma unroll
    for (int i = 0; i < 8; i++) {
        __half2 h = x[lane + 32 * i];
        v[2 * i]     = __low2float(h);
        v[2 * i + 1] = __high2float(h);
    }
    float mx = v[0];
#pragma unroll
    for (int i = 1; i < 16; i++) mx = fmaxf(mx, v[i]);
    mx = warpReduceMaxF(mx);

    float e[16];
    float sm = 0.f;
#pragma unroll
    for (int i = 0; i < 16; i++) { e[i] = __expf(v[i] - mx); sm += e[i]; }
    sm = warpReduceSumF(sm);
    float lse = __logf(sm);

    float* she = sh_e[wid];
    float2* lp2 = (float2*)(lp_out + (size_t)row * V_);
#pragma unroll
    for (int i = 0; i < 8; i++) {
        int c = lane + 32 * i;
        ((float2*)she)[c] = make_float2(e[2 * i], e[2 * i + 1]);
        lp2[c] = make_float2(v[2 * i] - mx - lse, v[2 * i + 1] - mx - lse);
    }
    __syncwarp();

    const int* tg = targets + b * L_;
    float pm = 0.f;
    for (int s = lane; s < S_; s += 32) {
        int lab = (s & 1) ? tg[s >> 1] : 1;
        pm = fmaxf(pm, she[lab]);
    }
    pm = warpReduceMaxF(pm);
    float inv = 1.0f / pm;
    __half* Pr = Pext + (size_t)row * SP_;
    for (int s = lane; s < S_; s += 32) {
        int lab = (s & 1) ? tg[s >> 1] : 1;
        Pr[s] = __float2half_rn(she[lab] * inv);
    }
    if (lane == 0 && t < olen[b])
        atomicAdd(&Msum[b], __logf(pm) - lse);
}

// -------------------- lengths (also zeroes Msum) ----------------------------
__global__ __launch_bounds__(256) void lengths_kernel(
    const int* __restrict__ encm, const int* __restrict__ tgtm,
    float* __restrict__ out, int len_off, int loss_off,
    int* __restrict__ tlen, int* __restrict__ olen, float* __restrict__ Msum)
{
    const int b = blockIdx.x, tid = threadIdx.x;
    const int lane = tid & 31, wid = tid >> 5;
    int c1 = 0;
    for (int i = tid; i < SSRC; i += 256) c1 += (encm[b * SSRC + i] != 0);
    int c2 = 0;
    for (int i = tid; i < L_; i += 256) c2 += (tgtm[b * L_ + i] != 0);
    c1 = warpReduceSumI(c1);
    c2 = warpReduceSumI(c2);
    __shared__ int redi[16];
    if (lane == 0) { redi[wid] = c1; redi[8 + wid] = c2; }
    __syncthreads();
    if (tid == 0) {
        int a = 0, t = 0;
#pragma unroll
        for (int i = 0; i < 8; i++) { a += redi[i]; t += redi[8 + i]; }
        olen[b] = STR_ * a;
        tlen[b] = t;
        Msum[b] = 0.f;
        out[len_off + b] = (float)(STR_ * a);
        if (b == 0) out[loss_off] = 0.f;
    }
}

// -------------------- CTC forward DP (2 steps per barrier) ------------------
__global__ __launch_bounds__(544) void ctc_dp_kernel(
    const __half* __restrict__ Pext, const float* __restrict__ Msum,
    const int* __restrict__ targets, const int* __restrict__ tlen,
    const int* __restrict__ olen, float* __restrict__ loss_slot)
{
    const int b = blockIdx.x;
    const int tid = threadIdx.x;
    __shared__ float sA[548], sB[548];     // 4 pads + 544 states
    __shared__ __align__(16) __half bufh[2][CH_][SP_];
    __shared__ float warpred[17];
    __shared__ float s_inv;

    const int s = tid;
    const bool active = (s < S_);
    const int inlen = olen[b];
    const int tl = tlen[b];

    bool k0 = false, k1 = false, k2 = false;
    {
        const int* tg = targets + b * L_;
#define SKIPAT(x, out)                                                        \
        if ((x) >= 1 && ((x) & 1)) {                                          \
            int l = (x) >> 1;                                                 \
            int tc = tg[l];                                                   \
            out = (tc != 1) && (l == 0 || tc != tg[l - 1]);                   \
        }
        if (active) { SKIPAT(s, k0); SKIPAT(s - 1, k1); SKIPAT(s - 2, k2); }
#undef SKIPAT
    }

    sA[tid] = 0.f; sB[tid] = 0.f;
    if (tid < 4) { sA[544 + tid] = 0.f; sB[544 + tid] = 0.f; }

    const __half* Pb = Pext + (size_t)b * T_ * SP_;
    {
        const int li0 = tid, li1 = tid + 544;
        uint4 r0, r1;
        if (li0 < 1040) r0 = ((const uint4*)Pb)[li0];
        if (li1 < 1040) r1 = ((const uint4*)Pb)[li1];
        if (li0 < 1040) ((uint4*)&bufh[0][0][0])[li0] = r0;
        if (li1 < 1040) ((uint4*)&bufh[0][0][0])[li1] = r1;
    }
    __syncthreads();

    float* cur = sA;
    float* nxt = sB;
    if (active) {
        float P0 = __half2float(bufh[0][0][s]);
        cur[4 + s] = (s == 0 || (s == 1 && tl > 0)) ? P0 : 0.f;
    }
    __syncthreads();

    const int sm1 = (s >= 1) ? s - 1 : 0;
    const int sm2 = (s >= 2) ? s - 2 : 0;

    float Cacc = 0.f;
    uint4 rp;
    const bool ldact = (tid < 520);
#pragma unroll 1
    for (int c = 0; c < NC_; c++) {
        if (c + 2 < NC_ && ldact)
            rp = ((const uint4*)(Pb + (size_t)(c + 2) * CH_ * SP_))[tid];
        const int cb = c & 1;
#pragma unroll
        for (int q = 0; q < 4; q++) {
            const int t1 = 8 * c + 2 * q + 1;
            const int t2 = t1 + 1;
            if (active) {
                float a0 = cur[4 + s];
                float a1 = cur[3 + s];
                float a2 = cur[2 + s];
                float a3 = cur[1 + s];
                float a4 = cur[s];
                const __half* row1 = &bufh[cb][2 * q + 1][0];
                float P1s  = __half2float(row1[s]);
                float P1m1 = __half2float(row1[sm1]);
                float P1m2 = __half2float(row1[sm2]);
                float P2s  = (q < 3) ? __half2float(bufh[cb][2 * q + 2][s])
                                     : __half2float(bufh[cb ^ 1][0][s]);
                bool fr1 = (t1 >= inlen);
                bool fr2 = (t2 >= inlen);
                float v1s  = fr1 ? a0 : (a0 + a1 + (k0 ? a2 : 0.f)) * P1s;
                float v1m1 = fr1 ? a1 : (a1 + a2 + (k1 ? a3 : 0.f)) * P1m1;
                float v1m2 = fr1 ? a2 : (a2 + a3 + (k2 ? a4 : 0.f)) * P1m2;
                float v2s  = fr2 ? v1s : (v1s + v1m1 + (k0 ? v1m2 : 0.f)) * P2s;
                nxt[4 + s] = v2s;
            }
            __syncthreads();
            { float* tmp = cur; cur = nxt; nxt = tmp; }
        }
        if (c + 2 < NC_ && ldact)
            ((uint4*)&bufh[cb][0][0])[tid] = rp;
        if (cb == 1) {
            float mv = active ? cur[4 + s] : 0.f;
            mv = warpReduceMaxF(mv);
            if ((tid & 31) == 0) warpred[tid >> 5] = mv;
            __syncthreads();
            if (tid == 0) {
                float r = warpred[0];
#pragma unroll
                for (int i = 1; i < 17; i++) r = fmaxf(r, warpred[i]);
                if (r > 0.f) { s_inv = 1.0f / r; Cacc += __logf(r); }
                else s_inv = 1.0f;
            }
            __syncthreads();
            if (active) cur[4 + s] *= s_inv;
            __syncthreads();
        }
    }

    if (tid == 0) {
        int il2 = 2 * tl;
        float al = cur[4 + il2];
        float ap = (tl > 0) ? cur[3 + il2] : 0.f;
        float per = -(__logf(al + ap) + Cacc + Msum[b]);
        float tld = (float)(tl > 0 ? tl : 1);
        atomicAdd(loss_slot, per / (tld * (float)B_));
    }
}

__global__ void finalize_kernel(float* out, int loss_off)
{
    float v = out[loss_off];
    if (!isfinite(v)) out[loss_off] = 0.f;
}

// -------------------- launch ------------------------------------------------
extern "C" void kernel_launch(void* const* d_in, const int* in_sizes, int n_in,
                              void* d_out, int out_size)
{
    const float* rep  = (const float*)d_in[0];
    const int*   encm = (const int*)d_in[1];
    const int*   tgt  = (const int*)d_in[2];
    const int*   tgtm = (const int*)d_in[3];
    const float* Wexp = (const float*)d_in[4];
    const float* bexp = (const float*)d_in[5];
    const float* W1   = (const float*)d_in[6];
    const float* b1   = (const float*)d_in[7];
    const float* W2   = (const float*)d_in[8];
    const float* b2   = (const float*)d_in[9];
    float* out = (float*)d_out;

    __half *p_repf, *p_Wexpf, *p_W1t, *p_W2t, *p_Bc, *p_H, *p_logitsh, *p_Pexth;
    float *p_bc, *p_zb, *p_Msum;
    int *p_tlen, *p_olen;
    cudaGetSymbolAddress((void**)&p_repf, g_repf);
    cudaGetSymbolAddress((void**)&p_Wexpf, g_Wexpf);
    cudaGetSymbolAddress((void**)&p_W1t, g_W1t);
    cudaGetSymbolAddress((void**)&p_W2t, g_W2t);
    cudaGetSymbolAddress((void**)&p_Bc, g_Bc);
    cudaGetSymbolAddress((void**)&p_bc, g_bc);
    cudaGetSymbolAddress((void**)&p_zb, g_zb);
    cudaGetSymbolAddress((void**)&p_H, g_H);
    cudaGetSymbolAddress((void**)&p_logitsh, g_logitsh);
    cudaGetSymbolAddress((void**)&p_Pexth, g_Pexth);
    cudaGetSymbolAddress((void**)&p_Msum, g_Msum);
    cudaGetSymbolAddress((void**)&p_tlen, g_tlen);
    cudaGetSymbolAddress((void**)&p_olen, g_olen);

    const int SMEM_GEMM = 3 * 32768;  // 96 KB -> 2 CTAs/SM
    cudaFuncSetAttribute(gemm_f16<false>, cudaFuncAttributeMaxDynamicSharedMemorySize, SMEM_GEMM);
    cudaFuncSetAttribute(gemm_f16<true >, cudaFuncAttributeMaxDynamicSharedMemorySize, SMEM_GEMM);

    // conversions
    conv_f16_kernel<<<8192, 256>>>(rep, p_repf);           // 16384x512
    conv_f16_kernel<<<1024, 256>>>(Wexp, p_Wexpf);         // 512x2048
    wtrans_kernel<<<dim3(1024 / 32, 512 / 32), 256>>>(W1, p_W1t, 512, 1024);
    wtrans_kernel<<<dim3(512 / 32, 1024 / 32), 256>>>(W2, p_W2t, 1024, 512);
    bias_fold_kernel<<<4, 1024>>>(bexp, W1, b1, p_bc);

    // merged weight Bc: single launch, blockIdx.z = r
    gemm_f16<false><<<dim3(4, 8, 4), 256, SMEM_GEMM>>>(
        p_W1t, 512, p_Wexpf, 2048, p_zb,
        p_Bc, 1024, 512, 512, /*bzs=*/512, /*czs=*/1024 * 512);

    // merged GEMM: H[16384,4096] = relu(rep @ Bc^T + bc)  (fp16 out)
    gemm_f16<true><<<dim3(32, 128, 1), 256, SMEM_GEMM>>>(
        p_repf, 512, p_Bc, 512, p_bc, p_H, 16384, 4096, 512, 0, 0);
    // GEMM3: logits[65536,512] = H @ W2 + b2  (fp16 out); H viewed as [65536,1024]
    gemm_f16<false><<<dim3(4, 512, 1), 256, SMEM_GEMM>>>(
        p_H, 1024, p_W2t, 1024, b2, p_logitsh, 65536, 512, 1024, 0, 0);

    const int loss_off = out_size - 1;
    const int len_off  = out_size - 1 - B_;
    lengths_kernel<<<B_, 256>>>(encm, tgtm, out, len_off, loss_off, p_tlen, p_olen, p_Msum);
    softmax_gather_kernel<<<B_ * T_ / 8, 256>>>(p_logitsh, tgt, out, p_Pexth, p_olen, p_Msum);
    ctc_dp_kernel<<<B_, 544>>>(p_Pexth, p_Msum, tgt, p_tlen, p_olen, out + loss_off);
    finalize_kernel<<<1, 1>>>(out, loss_off);
}